// round 12
// baseline (speedup 1.0000x reference)
#include <cuda_runtime.h>
#include <cuda_fp16.h>
#include <cstdint>
#include <cstddef>

#define TOK   4096
#define SEQ   2048
#define HID   1024
#define NHEAD 16
#define NEXP  8
#define FDIM  4096
#define NSLOT 8192

// ---------------- scratch ----------------
__device__ __align__(128) __half gb_hln [(size_t)TOK * HID];
__device__ __align__(128) __half gb_qkvw[(size_t)3 * HID * HID];
__device__ __align__(128) __half gb_outw[(size_t)HID * HID];
__device__ __align__(128) __half gb_w1t [(size_t)NEXP * FDIM * HID];
__device__ __align__(128) __half gb_w2t [(size_t)NEXP * HID * FDIM];
__device__ __align__(128) __half gb_qkv [(size_t)TOK * 3 * HID];
__device__ __align__(128) __half gb_vT  [(size_t)2 * NHEAD * 64 * SEQ];
__device__ __align__(128) __half gb_ao  [(size_t)TOK * HID];
__device__ __align__(128) __half gb_h2  [(size_t)TOK * HID];
__device__ __align__(128) __half gb_H1  [(size_t)NSLOT * FDIM];
__device__ float g_xattn[(size_t)TOK * HID];
__device__ float g_Y2   [(size_t)NSLOT * HID];
__device__ int   g_topi [TOK * 2];
__device__ float g_topw [TOK * 2];
__device__ int   g_cnt  [NEXP];
__device__ int   g_offs [NEXP + 1];
__device__ int   g_cur  [NEXP];
__device__ int   g_slottok[NSLOT];
__device__ int   g_slotof [TOK * 2];

// ---------------- PTX helpers ----------------
__device__ __forceinline__ uint32_t s2u(const void* p) {
    uint32_t a;
    asm("{ .reg .u64 t; cvta.to.shared.u64 t, %1; cvt.u32.u64 %0, t; }" : "=r"(a) : "l"(p));
    return a;
}
__device__ __forceinline__ void cpasync16(uint32_t saddr, const void* g) {
    asm volatile("cp.async.cg.shared.global [%0], [%1], 16;" :: "r"(saddr), "l"(g));
}
#define CP_COMMIT() asm volatile("cp.async.commit_group;" ::: "memory")
#define CP_WAIT(n)  asm volatile("cp.async.wait_group %0;" :: "n"(n) : "memory")

__device__ __forceinline__ void ldsm4(uint32_t* r, uint32_t addr) {
    asm volatile("ldmatrix.sync.aligned.m8n8.x4.shared.b16 {%0,%1,%2,%3}, [%4];"
                 : "=r"(r[0]), "=r"(r[1]), "=r"(r[2]), "=r"(r[3]) : "r"(addr));
}
__device__ __forceinline__ void mma16816(float* c, const uint32_t* a, const uint32_t* b) {
    asm volatile("mma.sync.aligned.m16n8k16.row.col.f32.f16.f16.f32 "
                 "{%0,%1,%2,%3}, {%4,%5,%6,%7}, {%8,%9}, {%0,%1,%2,%3};"
                 : "+f"(c[0]), "+f"(c[1]), "+f"(c[2]), "+f"(c[3])
                 : "r"(a[0]), "r"(a[1]), "r"(a[2]), "r"(a[3]), "r"(b[0]), "r"(b[1]));
}
__device__ __forceinline__ float gelu_tanh(float x) {
    float u = 0.7978845608028654f * (x + 0.044715f * x * x * x);
    u = fminf(fmaxf(u, -15.0f), 15.0f);
    float e = __expf(2.0f * u);
    return x * e / (e + 1.0f);
}
__device__ __forceinline__ uint32_t pkh2(float a, float b) {
    __half2 t = __floats2half2_rn(a, b);
    return *(uint32_t*)&t;
}

// ---------------- HMMA GEMM: 4-stage cp.async ring, NT=128, occ 2 ----------------
// MODE 0: QKV (+bias; q/k -> gb_qkv, v -> gb_vT transposed)
// MODE 1: outproj (+bias+res, f32 out)
// MODE 4: MoE1 (gather rows, +b1, gelu, f16 out)   MODE 5: MoE2 (+b2, f32 out)
#define STAGES 4
template <int MODE, int NT>
__global__ void __launch_bounds__(256, 2) hgemm(
    const __half* __restrict__ A, const __half* __restrict__ B, void* Cv,
    int M, int N, int K, int lda, int ldb, int ldc,
    const float* __restrict__ bias, const float* __restrict__ res,
    const int* __restrict__ gtok, const int* __restrict__ offs) {
    extern __shared__ __align__(128) char dsm[];
    constexpr uint32_t AST = 128 * 40 * 2;
    constexpr uint32_t BST = NT * 40 * 2;

    int tid = threadIdx.x, wid = tid >> 5, lid = tid & 31;
    int z = blockIdx.z;
    const __half* Ab = A;
    const __half* Bb = B;
    float* Cf = (float*)Cv;
    __half* Cb = (__half*)Cv;
    const float* biasb = bias;
    int r0 = 0, r1 = M;
    if (MODE == 4 || MODE == 5) {
        r0 = offs[z]; r1 = offs[z + 1];
        Bb = B + (size_t)z * (size_t)N * K;
        biasb = bias + (size_t)z * N;
    }
    int rowBase = r0 + blockIdx.y * 128;
    if (rowBase >= r1) return;
    int n0 = blockIdx.x * NT;

    constexpr int WN = NT / 4;
    constexpr int NTILES = WN / 8;
    int wm = (wid >> 2) * 64;
    int wn = (wid & 3) * WN;

    uint32_t uAs = s2u(dsm);
    uint32_t uBs = uAs + STAGES * AST;

    int aRowL = wm + (lid & 15);
    int aColL = (lid >> 4) * 8;
    int bRowL = wn + ((lid >> 4) << 3) + (lid & 7);
    int bColL = ((lid >> 3) & 1) * 8;

    float acc[4][NTILES][4];
#pragma unroll
    for (int i = 0; i < 4; i++)
#pragma unroll
        for (int j = 0; j < NTILES; j++)
#pragma unroll
            for (int q = 0; q < 4; q++) acc[i][j][q] = 0.f;

    int ldRow = tid >> 2, ldCh = tid & 3;
    int gr0 = rowBase + ldRow;       if (gr0 > r1 - 1) gr0 = r1 - 1;
    int gr1 = rowBase + ldRow + 64;  if (gr1 > r1 - 1) gr1 = r1 - 1;
    const __half* aSrc0;
    const __half* aSrc1;
    if (MODE == 4) { aSrc0 = Ab + (size_t)gtok[gr0] * lda; aSrc1 = Ab + (size_t)gtok[gr1] * lda; }
    else           { aSrc0 = Ab + (size_t)gr0 * lda;        aSrc1 = Ab + (size_t)gr1 * lda; }

    auto loadStage = [&](int st, int c) {
        int kt = c * 32;
        cpasync16(uAs + st * AST + ldRow * 80 + ldCh * 16,        aSrc0 + kt + ldCh * 8);
        cpasync16(uAs + st * AST + (ldRow + 64) * 80 + ldCh * 16, aSrc1 + kt + ldCh * 8);
#pragma unroll
        for (int i = 0; i < NT / 64; i++) {
            int idx = tid + i * 256;
            int row = idx >> 2, ch = idx & 3;
            cpasync16(uBs + st * BST + row * 80 + ch * 16,
                      Bb + (size_t)(n0 + row) * ldb + kt + ch * 8);
        }
    };

    int nk = K / 32;
    loadStage(0, 0); CP_COMMIT();
    loadStage(1, 1); CP_COMMIT();
    loadStage(2, 2); CP_COMMIT();

    for (int c = 0; c < nk; c++) {
        CP_WAIT(2);
        __syncthreads();
        if (c + 3 < nk) loadStage((c + 3) & (STAGES - 1), c + 3);
        CP_COMMIT();   // always commit — keeps wait invariant at the tail
        int st = c & (STAGES - 1);
        uint32_t aBase = uAs + st * AST;
        uint32_t bBase = uBs + st * BST;
#pragma unroll
        for (int ks = 0; ks < 2; ks++) {
            uint32_t afr[4][4];
#pragma unroll
            for (int mt = 0; mt < 4; mt++)
                ldsm4(afr[mt], aBase + (aRowL + mt * 16) * 80 + (ks * 16 + aColL) * 2);
#pragma unroll
            for (int nb = 0; nb < NTILES / 2; nb++) {
                uint32_t bfr[4];
                ldsm4(bfr, bBase + (bRowL + nb * 16) * 80 + (ks * 16 + bColL) * 2);
#pragma unroll
                for (int mt = 0; mt < 4; mt++) {
                    mma16816(acc[mt][2 * nb],     afr[mt], &bfr[0]);
                    mma16816(acc[mt][2 * nb + 1], afr[mt], &bfr[2]);
                }
            }
        }
    }

#pragma unroll
    for (int mt = 0; mt < 4; mt++) {
#pragma unroll
        for (int h = 0; h < 2; h++) {
            int row = rowBase + wm + mt * 16 + h * 8 + (lid >> 2);
            if (row >= r1) continue;
#pragma unroll
            for (int nt = 0; nt < NTILES; nt++) {
                float v0 = acc[mt][nt][2 * h], v1 = acc[mt][nt][2 * h + 1];
                int cc = n0 + wn + nt * 8 + 2 * (lid & 3);
                if (MODE == 0) { v0 += bias[cc]; v1 += bias[cc + 1]; }
                if (MODE == 1) {
                    float2 rr = *(const float2*)(res + (size_t)row * ldc + cc);
                    v0 += bias[cc] + rr.x; v1 += bias[cc + 1] + rr.y;
                }
                if (MODE == 4) {
                    v0 = gelu_tanh(v0 + biasb[cc]);
                    v1 = gelu_tanh(v1 + biasb[cc + 1]);
                }
                if (MODE == 5) { v0 += biasb[cc]; v1 += biasb[cc + 1]; }
                if (MODE == 1 || MODE == 5) {
                    *(float2*)(Cf + (size_t)row * ldc + cc) = make_float2(v0, v1);
                } else if (MODE == 0 && cc >= 2 * HID) {
                    // V-section: write straight into per-head V^T (fused vtrans)
                    int d = cc - 2 * HID;
                    int hh = d >> 6, dd = d & 63;
                    int bb = row >> 11, ss = row & 2047;
                    uint32_t pk = pkh2(v0, v1);
                    __half2 pr = *(__half2*)&pk;
                    __half* vb = gb_vT + ((size_t)(bb * NHEAD + hh) * 64 + dd) * SEQ + ss;
                    vb[0]   = __low2half(pr);
                    vb[SEQ] = __high2half(pr);
                } else {
                    *(uint32_t*)(Cb + (size_t)row * ldc + cc) = pkh2(v0, v1);
                }
            }
        }
    }
}

// ---------------- fused flash attention ----------------
__global__ void __launch_bounds__(256, 1) flash_k(const __half* __restrict__ qkv,
                                                  const __half* __restrict__ vT,
                                                  __half* __restrict__ ao) {
    extern __shared__ char dyn[];
    constexpr uint32_t QBYTES = 128 * 72 * 2;
    constexpr uint32_t KST    = 128 * 72 * 2;
    constexpr uint32_t VST    = 64 * 136 * 2;
    char* sQ = dyn;
    char* sK = dyn + QBYTES;
    char* sV = dyn + QBYTES + 2 * KST;

    int tid = threadIdx.x, wid = tid >> 5, lid = tid & 31;
    int qt = blockIdx.x, bh = blockIdx.y;
    int b = bh >> 4, h = bh & 15;
    int q0 = qt * 128;
    const __half* Qg = qkv + (size_t)b * SEQ * 3 * HID + h * 64;
    const __half* Kg = qkv + (size_t)b * SEQ * 3 * HID + HID + h * 64;
    const __half* Vt = vT + (size_t)bh * 64 * SEQ;

    uint32_t uQ = s2u(sQ), uK = s2u(sK), uV = s2u(sV);

#pragma unroll
    for (int i = 0; i < 4; i++) {
        int idx = tid + i * 256;
        int row = idx >> 3, ch = idx & 7;
        cpasync16(uQ + row * 144 + ch * 16, Qg + (size_t)(q0 + row) * 3 * HID + ch * 8);
    }
    auto loadKV = [&](int st, int kt) {
#pragma unroll
        for (int i = 0; i < 4; i++) {
            int idx = tid + i * 256;
            int row = idx >> 3, ch = idx & 7;
            cpasync16(uK + st * KST + row * 144 + ch * 16,
                      Kg + (size_t)(kt * 128 + row) * 3 * HID + ch * 8);
        }
#pragma unroll
        for (int i = 0; i < 4; i++) {
            int idx = tid + i * 256;
            int row = idx >> 4, ch = idx & 15;
            cpasync16(uV + st * VST + row * 272 + ch * 16,
                      Vt + (size_t)row * SEQ + kt * 128 + ch * 8);
        }
    };
    loadKV(0, 0);
    CP_COMMIT();

    float oacc[8][4];
#pragma unroll
    for (int j = 0; j < 8; j++)
#pragma unroll
        for (int q = 0; q < 4; q++) oacc[j][q] = 0.f;
    float m0 = -1e30f, m1 = -1e30f, l0 = 0.f, l1 = 0.f;

    int aRowL = wid * 16 + (lid & 15);
    int aColL = (lid >> 4) * 8;
    int bRowL = ((lid >> 4) << 3) + (lid & 7);
    int bColL = ((lid >> 3) & 1) * 8;

    for (int kt = 0; kt < SEQ / 128; kt++) {
        if (kt + 1 < SEQ / 128) { loadKV((kt + 1) & 1, kt + 1); CP_COMMIT(); CP_WAIT(1); }
        else CP_WAIT(0);
        __syncthreads();
        int st = kt & 1;
        uint32_t kBase = uK + st * KST;
        uint32_t vBase = uV + st * VST;

        float sacc[16][4];
#pragma unroll
        for (int t = 0; t < 16; t++)
#pragma unroll
            for (int q = 0; q < 4; q++) sacc[t][q] = 0.f;

#pragma unroll
        for (int ks = 0; ks < 4; ks++) {
            uint32_t afr[4];
            ldsm4(afr, uQ + aRowL * 144 + (ks * 16 + aColL) * 2);
#pragma unroll
            for (int nb = 0; nb < 8; nb++) {
                uint32_t bfr[4];
                ldsm4(bfr, kBase + (nb * 16 + bRowL) * 144 + (ks * 16 + bColL) * 2);
                mma16816(sacc[2 * nb],     afr, &bfr[0]);
                mma16816(sacc[2 * nb + 1], afr, &bfr[2]);
            }
        }

        float tm0 = -1e30f, tm1 = -1e30f;
#pragma unroll
        for (int t = 0; t < 16; t++) {
            sacc[t][0] *= 0.125f; sacc[t][1] *= 0.125f;
            sacc[t][2] *= 0.125f; sacc[t][3] *= 0.125f;
            tm0 = fmaxf(tm0, fmaxf(sacc[t][0], sacc[t][1]));
            tm1 = fmaxf(tm1, fmaxf(sacc[t][2], sacc[t][3]));
        }
        tm0 = fmaxf(tm0, __shfl_xor_sync(0xffffffffu, tm0, 1));
        tm0 = fmaxf(tm0, __shfl_xor_sync(0xffffffffu, tm0, 2));
        tm1 = fmaxf(tm1, __shfl_xor_sync(0xffffffffu, tm1, 1));
        tm1 = fmaxf(tm1, __shfl_xor_sync(0xffffffffu, tm1, 2));
        float nm0 = fmaxf(m0, tm0), nm1 = fmaxf(m1, tm1);
        float f0 = __expf(m0 - nm0), f1 = __expf(m1 - nm1);
        m0 = nm0; m1 = nm1;
        float rs0 = 0.f, rs1 = 0.f;
#pragma unroll
        for (int t = 0; t < 16; t++) {
            sacc[t][0] = __expf(sacc[t][0] - nm0);
            sacc[t][1] = __expf(sacc[t][1] - nm0);
            sacc[t][2] = __expf(sacc[t][2] - nm1);
            sacc[t][3] = __expf(sacc[t][3] - nm1);
            rs0 += sacc[t][0] + sacc[t][1];
            rs1 += sacc[t][2] + sacc[t][3];
        }
        rs0 += __shfl_xor_sync(0xffffffffu, rs0, 1);
        rs0 += __shfl_xor_sync(0xffffffffu, rs0, 2);
        rs1 += __shfl_xor_sync(0xffffffffu, rs1, 1);
        rs1 += __shfl_xor_sync(0xffffffffu, rs1, 2);
        l0 = l0 * f0 + rs0;
        l1 = l1 * f1 + rs1;
#pragma unroll
        for (int j = 0; j < 8; j++) {
            oacc[j][0] *= f0; oacc[j][1] *= f0;
            oacc[j][2] *= f1; oacc[j][3] *= f1;
        }

#pragma unroll
        for (int ks = 0; ks < 8; ks++) {
            uint32_t pa[4];
            pa[0] = pkh2(sacc[2 * ks][0],     sacc[2 * ks][1]);
            pa[1] = pkh2(sacc[2 * ks][2],     sacc[2 * ks][3]);
            pa[2] = pkh2(sacc[2 * ks + 1][0], sacc[2 * ks + 1][1]);
            pa[3] = pkh2(sacc[2 * ks + 1][2], sacc[2 * ks + 1][3]);
#pragma unroll
            for (int nb = 0; nb < 4; nb++) {
                uint32_t bfr[4];
                ldsm4(bfr, vBase + (nb * 16 + bRowL) * 272 + (ks * 16 + bColL) * 2);
                mma16816(oacc[2 * nb],     pa, &bfr[0]);
                mma16816(oacc[2 * nb + 1], pa, &bfr[2]);
            }
        }
        __syncthreads();
    }

    float i0 = 1.0f / l0, i1 = 1.0f / l1;
    int row = q0 + wid * 16 + (lid >> 2);
    __half* d0 = ao + ((size_t)b * SEQ + row) * HID + h * 64;
    __half* d1 = ao + ((size_t)b * SEQ + row + 8) * HID + h * 64;
#pragma unroll
    for (int j = 0; j < 8; j++) {
        int cc = j * 8 + (lid & 3) * 2;
        *(uint32_t*)(d0 + cc) = pkh2(oacc[j][0] * i0, oacc[j][1] * i0);
        *(uint32_t*)(d1 + cc) = pkh2(oacc[j][2] * i1, oacc[j][3] * i1);
    }
}

// ---------------- support kernels ----------------
__global__ void __launch_bounds__(256) f2h_k(const float* __restrict__ in, __half* __restrict__ outp, int n4) {
    int i = blockIdx.x * 256 + threadIdx.x;
    if (i >= n4) return;
    float4 v = ((const float4*)in)[i];
    ((uint2*)outp)[i] = make_uint2(pkh2(v.x, v.y), pkh2(v.z, v.w));
}

__global__ void tconv_k(const float* __restrict__ in, __half* __restrict__ outp, int R, int C) {
    __shared__ float t[32][33];
    in += (size_t)blockIdx.z * R * C;
    outp += (size_t)blockIdx.z * R * C;
    int x = blockIdx.x * 32 + threadIdx.x;
    int y0 = blockIdx.y * 32;
#pragma unroll
    for (int j = 0; j < 32; j += 8)
        t[threadIdx.y + j][threadIdx.x] = in[(size_t)(y0 + threadIdx.y + j) * C + x];
    __syncthreads();
    int ox = y0 + threadIdx.x;
    int oy0 = blockIdx.x * 32;
#pragma unroll
    for (int j = 0; j < 32; j += 8)
        outp[(size_t)(oy0 + threadIdx.y + j) * R + ox] = __float2half_rn(t[threadIdx.x][threadIdx.y + j]);
}

// LN1: f32 -> f16 only
__global__ void __launch_bounds__(256) ln_k(const float* __restrict__ x, const float* __restrict__ g,
                                            const float* __restrict__ bta, __half* __restrict__ ob) {
    __shared__ float red[16], fin[2];
    int tid = threadIdx.x;
    size_t row = blockIdx.x;
    float4 v = ((const float4*)(x + row * HID))[tid];
    float s = v.x + v.y + v.z + v.w;
    float q = v.x * v.x + v.y * v.y + v.z * v.z + v.w * v.w;
#pragma unroll
    for (int o = 16; o; o >>= 1) {
        s += __shfl_xor_sync(0xffffffffu, s, o);
        q += __shfl_xor_sync(0xffffffffu, q, o);
    }
    if ((tid & 31) == 0) { red[tid >> 5] = s; red[8 + (tid >> 5)] = q; }
    __syncthreads();
    if (tid < 8) {
        s = red[tid]; q = red[8 + tid];
#pragma unroll
        for (int o = 4; o; o >>= 1) {
            s += __shfl_xor_sync(0xffu, s, o);
            q += __shfl_xor_sync(0xffu, q, o);
        }
        if (tid == 0) {
            float mu = s * (1.0f / HID);
            fin[0] = mu;
            fin[1] = rsqrtf(q * (1.0f / HID) - mu * mu + 1e-5f);
        }
    }
    __syncthreads();
    float mu = fin[0], rstd = fin[1];
    float4 gv = ((const float4*)g)[tid];
    float4 bv = ((const float4*)bta)[tid];
    float4 o;
    o.x = (v.x - mu) * rstd * gv.x + bv.x;
    o.y = (v.y - mu) * rstd * gv.y + bv.y;
    o.z = (v.z - mu) * rstd * gv.z + bv.z;
    o.w = (v.w - mu) * rstd * gv.w + bv.w;
    ((uint2*)(ob + row * HID))[tid] = make_uint2(pkh2(o.x, o.y), pkh2(o.z, o.w));
}

// LN2 fused with MoE gating: normalize, emit f16 row, compute fp32 gate
// logits in-block, top-2 + softmax weights + expert counts.
__global__ void __launch_bounds__(256) ln_gate_k(const float* __restrict__ x,
                                                 const float* __restrict__ g,
                                                 const float* __restrict__ bta,
                                                 const float* __restrict__ Wg,
                                                 __half* __restrict__ ob) {
    __shared__ float red[16], fin[2];
    __shared__ float gred[8][8];   // [warp][expert]
    __shared__ float glog[8];
    int tid = threadIdx.x;
    size_t row = blockIdx.x;
    float4 v = ((const float4*)(x + row * HID))[tid];
    float s = v.x + v.y + v.z + v.w;
    float q = v.x * v.x + v.y * v.y + v.z * v.z + v.w * v.w;
#pragma unroll
    for (int o = 16; o; o >>= 1) {
        s += __shfl_xor_sync(0xffffffffu, s, o);
        q += __shfl_xor_sync(0xffffffffu, q, o);
    }
    if ((tid & 31) == 0) { red[tid >> 5] = s; red[8 + (tid >> 5)] = q; }
    __syncthreads();
    if (tid < 8) {
        s = red[tid]; q = red[8 + tid];
#pragma unroll
        for (int o = 4; o; o >>= 1) {
            s += __shfl_xor_sync(0xffu, s, o);
            q += __shfl_xor_sync(0xffu, q, o);
        }
        if (tid == 0) {
            float mu = s * (1.0f / HID);
            fin[0] = mu;
            fin[1] = rsqrtf(q * (1.0f / HID) - mu * mu + 1e-5f);
        }
    }
    __syncthreads();
    float mu = fin[0], rstd = fin[1];
    float4 gv = ((const float4*)g)[tid];
    float4 bv = ((const float4*)bta)[tid];
    float o[4];
    o[0] = (v.x - mu) * rstd * gv.x + bv.x;
    o[1] = (v.y - mu) * rstd * gv.y + bv.y;
    o[2] = (v.z - mu) * rstd * gv.z + bv.z;
    o[3] = (v.w - mu) * rstd * gv.w + bv.w;
    ((uint2*)(ob + row * HID))[tid] = make_uint2(pkh2(o[0], o[1]), pkh2(o[2], o[3]));

    // gate logits: acc[e] += o[j] * Wg[(tid*4+j)*8 + e]
    float acc[8] = {0, 0, 0, 0, 0, 0, 0, 0};
#pragma unroll
    for (int j = 0; j < 4; j++) {
        const float4* wr = (const float4*)(Wg + (size_t)(tid * 4 + j) * 8);
        float4 w0 = wr[0], w1 = wr[1];
        acc[0] += o[j] * w0.x; acc[1] += o[j] * w0.y; acc[2] += o[j] * w0.z; acc[3] += o[j] * w0.w;
        acc[4] += o[j] * w1.x; acc[5] += o[j] * w1.y; acc[6] += o[j] * w1.z; acc[7] += o[j] * w1.w;
    }
#pragma unroll
    for (int os = 16; os; os >>= 1)
#pragma unroll
        for (int e = 0; e < 8; e++) acc[e] += __shfl_xor_sync(0xffffffffu, acc[e], os);
    if ((tid & 31) == 0)
#pragma unroll
        for (int e = 0; e < 8; e++) gred[tid >> 5][e] = acc[e];
    __syncthreads();
    if (tid < 8) {
        float t = 0.f;
#pragma unroll
        for (int w = 0; w < 8; w++) t += gred[w][tid];
        glog[tid] = t;
    }
    __syncthreads();
    if (tid == 0) {
        int i0 = 0; float v0 = glog[0];
#pragma unroll
        for (int e = 1; e < 8; e++) if (glog[e] > v0) { v0 = glog[e]; i0 = e; }
        int i1 = -1; float v1 = -3.4e38f;
#pragma unroll
        for (int e = 0; e < 8; e++) if (e != i0 && glog[e] > v1) { v1 = glog[e]; i1 = e; }
        float w0 = 1.0f / (1.0f + __expf(v1 - v0));
        int t = (int)row;
        g_topi[2 * t] = i0; g_topi[2 * t + 1] = i1;
        g_topw[2 * t] = w0; g_topw[2 * t + 1] = 1.0f - w0;
        atomicAdd(&g_cnt[i0], 1);
        atomicAdd(&g_cnt[i1], 1);
    }
}

// merged scan + scatter (single block)
__global__ void __launch_bounds__(1024) route_k() {
    if (threadIdx.x == 0) {
        g_offs[0] = 0;
        for (int e = 0; e < NEXP; e++) g_offs[e + 1] = g_offs[e] + g_cnt[e];
    }
    __syncthreads();
    for (int idx = threadIdx.x; idx < TOK * 2; idx += 1024) {
        int e = g_topi[idx];
        int pos = atomicAdd(&g_cur[e], 1);
        int slot = g_offs[e] + pos;
        g_slottok[slot] = idx >> 1;
        g_slotof[idx] = slot;
    }
}

__global__ void __launch_bounds__(256) combine_k(float* __restrict__ outp) {
    int t = blockIdx.x;
    int j = threadIdx.x;
    float w0 = g_topw[2 * t], w1 = g_topw[2 * t + 1];
    size_t s0 = g_slotof[2 * t], s1 = g_slotof[2 * t + 1];
    float4 r  = ((const float4*)(g_xattn + (size_t)t * HID))[j];
    float4 y0 = ((const float4*)(g_Y2 + s0 * HID))[j];
    float4 y1 = ((const float4*)(g_Y2 + s1 * HID))[j];
    r.x += w0 * y0.x + w1 * y1.x;
    r.y += w0 * y0.y + w1 * y1.y;
    r.z += w0 * y0.z + w1 * y1.z;
    r.w += w0 * y0.w + w1 * y1.w;
    ((float4*)(outp + (size_t)t * HID))[j] = r;
}

#define SYM(p, s) void* p; cudaGetSymbolAddress(&p, s)

extern "C" void kernel_launch(void* const* d_in, const int* in_sizes, int n_in,
                              void* d_out, int out_size) {
    const float* x     = (const float*)d_in[0];
    const float* ln1_g = (const float*)d_in[1];
    const float* ln1_b = (const float*)d_in[2];
    const float* qkv_w = (const float*)d_in[3];
    const float* qkv_b = (const float*)d_in[4];
    const float* out_w = (const float*)d_in[5];
    const float* out_b = (const float*)d_in[6];
    const float* ln2_g = (const float*)d_in[7];
    const float* ln2_b = (const float*)d_in[8];
    const float* Wg    = (const float*)d_in[9];
    const float* W1    = (const float*)d_in[10];
    const float* b1    = (const float*)d_in[11];
    const float* W2    = (const float*)d_in[12];
    const float* b2    = (const float*)d_in[13];
    float* outp = (float*)d_out;

    SYM(p_hln, gb_hln);   SYM(p_qkvw, gb_qkvw); SYM(p_outw, gb_outw);
    SYM(p_w1t, gb_w1t);   SYM(p_w2t, gb_w2t);   SYM(p_qkv, gb_qkv);
    SYM(p_vT, gb_vT);     SYM(p_ao, gb_ao);     SYM(p_h2b, gb_h2);
    SYM(p_H1, gb_H1);     SYM(p_xattn, g_xattn);
    SYM(p_Y2, g_Y2);      SYM(p_cnt, g_cnt);    SYM(p_cur, g_cur);
    SYM(p_slottok, g_slottok); SYM(p_offs, g_offs);

    constexpr int GEMM_SMEM = STAGES * (128 + 128) * 40 * 2;  // 81920
    cudaFuncSetAttribute(hgemm<0, 128>, cudaFuncAttributeMaxDynamicSharedMemorySize, GEMM_SMEM);
    cudaFuncSetAttribute(hgemm<1, 128>, cudaFuncAttributeMaxDynamicSharedMemorySize, GEMM_SMEM);
    cudaFuncSetAttribute(hgemm<4, 128>, cudaFuncAttributeMaxDynamicSharedMemorySize, GEMM_SMEM);
    cudaFuncSetAttribute(hgemm<5, 128>, cudaFuncAttributeMaxDynamicSharedMemorySize, GEMM_SMEM);
    constexpr int FLASH_SMEM = (128 * 72 * 2) * 3 + (64 * 136 * 2) * 2;  // 90112
    cudaFuncSetAttribute(flash_k, cudaFuncAttributeMaxDynamicSharedMemorySize, FLASH_SMEM);

    cudaStream_t s2;
    cudaStreamCreateWithFlags(&s2, cudaStreamNonBlocking);
    cudaEvent_t evFork, evQkvw, evJoin;
    cudaEventCreateWithFlags(&evFork, cudaEventDisableTiming);
    cudaEventCreateWithFlags(&evQkvw, cudaEventDisableTiming);
    cudaEventCreateWithFlags(&evJoin, cudaEventDisableTiming);

    cudaEventRecord(evFork, 0);
    cudaStreamWaitEvent(s2, evFork, 0);

    dim3 tb(32, 8);
    // side stream: qkv_w convert (joined early), then MoE/outproj weights + counters
    f2h_k<<<(3 * HID * HID / 4 + 255) / 256, 256, 0, s2>>>(qkv_w, (__half*)p_qkvw, 3 * HID * HID / 4);
    cudaEventRecord(evQkvw, s2);
    tconv_k<<<dim3(FDIM / 32, HID / 32, NEXP), tb, 0, s2>>>(W1, (__half*)p_w1t, HID, FDIM);
    tconv_k<<<dim3(HID / 32, FDIM / 32, NEXP), tb, 0, s2>>>(W2, (__half*)p_w2t, FDIM, HID);
    f2h_k<<<(HID * HID / 4 + 255) / 256, 256, 0, s2>>>(out_w, (__half*)p_outw, HID * HID / 4);
    cudaMemsetAsync(p_cnt, 0, NEXP * sizeof(int), s2);
    cudaMemsetAsync(p_cur, 0, NEXP * sizeof(int), s2);
    cudaEventRecord(evJoin, s2);

    // main stream: LN1 overlaps the qkv_w conversion
    ln_k<<<TOK, 256>>>(x, ln1_g, ln1_b, (__half*)p_hln);
    cudaStreamWaitEvent(0, evQkvw, 0);

    // QKV GEMM: q/k -> gb_qkv, v -> gb_vT (fused transpose)
    hgemm<0, 128><<<dim3(3 * HID / 128, TOK / 128, 1), 256, GEMM_SMEM>>>(
        (const __half*)p_hln, (const __half*)p_qkvw, p_qkv,
        TOK, 3 * HID, HID, HID, HID, 3 * HID, qkv_b, nullptr, nullptr, nullptr);

    flash_k<<<dim3(SEQ / 128, 2 * NHEAD), 256, FLASH_SMEM>>>(
        (const __half*)p_qkv, (const __half*)p_vT, (__half*)p_ao);

    cudaStreamWaitEvent(0, evJoin, 0);

    hgemm<1, 128><<<dim3(HID / 128, TOK / 128, 1), 256, GEMM_SMEM>>>(
        (const __half*)p_ao, (const __half*)p_outw, p_xattn,
        TOK, HID, HID, HID, HID, HID, out_b, x, nullptr, nullptr);

    // LN2 + gating fused
    ln_gate_k<<<TOK, 256>>>((const float*)p_xattn, ln2_g, ln2_b, Wg, (__half*)p_h2b);
    route_k<<<1, 1024>>>();

    hgemm<4, 128><<<dim3(FDIM / 128, NSLOT / 128, NEXP), 256, GEMM_SMEM>>>(
        (const __half*)p_h2b, (const __half*)p_w1t, p_H1,
        0, FDIM, HID, HID, HID, FDIM, b1, nullptr, (const int*)p_slottok, (const int*)p_offs);

    hgemm<5, 128><<<dim3(HID / 128, NSLOT / 128, NEXP), 256, GEMM_SMEM>>>(
        (const __half*)p_H1, (const __half*)p_w2t, p_Y2,
        0, HID, FDIM, FDIM, FDIM, HID, b2, nullptr, nullptr, (const int*)p_offs);

    combine_k<<<TOK, 256>>>(outp);

    cudaStreamDestroy(s2);
    cudaEventDestroy(evFork);
    cudaEventDestroy(evQkvw);
    cudaEventDestroy(evJoin);
}

// round 13
// speedup vs baseline: 1.0037x; 1.0037x over previous
#include <cuda_runtime.h>
#include <cuda_fp16.h>
#include <cstdint>
#include <cstddef>

#define TOK   4096
#define SEQ   2048
#define HID   1024
#define NHEAD 16
#define NEXP  8
#define FDIM  4096
#define NSLOT 8192

// ---------------- scratch ----------------
__device__ __align__(128) __half gb_hln [(size_t)TOK * HID];
__device__ __align__(128) __half gb_qkvw[(size_t)3 * HID * HID];
__device__ __align__(128) __half gb_outw[(size_t)HID * HID];
__device__ __align__(128) __half gb_w1t [(size_t)NEXP * FDIM * HID];
__device__ __align__(128) __half gb_w2t [(size_t)NEXP * HID * FDIM];
__device__ __align__(128) __half gb_qkv [(size_t)TOK * 3 * HID];
__device__ __align__(128) __half gb_vT  [(size_t)2 * NHEAD * 64 * SEQ];
__device__ __align__(128) __half gb_ao  [(size_t)TOK * HID];
__device__ __align__(128) __half gb_h2  [(size_t)TOK * HID];
__device__ __align__(128) __half gb_H1  [(size_t)NSLOT * FDIM];
__device__ __align__(128) __half gb_Y2  [(size_t)NSLOT * HID];
__device__ float g_xattn[(size_t)TOK * HID];
__device__ float g_h2f  [(size_t)TOK * HID];
__device__ int   g_topi [TOK * 2];
__device__ float g_topw [TOK * 2];
__device__ int   g_cnt  [NEXP];
__device__ int   g_offs [NEXP + 1];
__device__ int   g_cur  [NEXP];
__device__ int   g_slottok[NSLOT];
__device__ int   g_slotof [TOK * 2];

// ---------------- PTX helpers ----------------
__device__ __forceinline__ uint32_t s2u(const void* p) {
    uint32_t a;
    asm("{ .reg .u64 t; cvta.to.shared.u64 t, %1; cvt.u32.u64 %0, t; }" : "=r"(a) : "l"(p));
    return a;
}
__device__ __forceinline__ void cpasync16(uint32_t saddr, const void* g) {
    asm volatile("cp.async.cg.shared.global [%0], [%1], 16;" :: "r"(saddr), "l"(g));
}
#define CP_COMMIT() asm volatile("cp.async.commit_group;" ::: "memory")
#define CP_WAIT(n)  asm volatile("cp.async.wait_group %0;" :: "n"(n) : "memory")

__device__ __forceinline__ void ldsm4(uint32_t* r, uint32_t addr) {
    asm volatile("ldmatrix.sync.aligned.m8n8.x4.shared.b16 {%0,%1,%2,%3}, [%4];"
                 : "=r"(r[0]), "=r"(r[1]), "=r"(r[2]), "=r"(r[3]) : "r"(addr));
}
__device__ __forceinline__ void mma16816(float* c, const uint32_t* a, const uint32_t* b) {
    asm volatile("mma.sync.aligned.m16n8k16.row.col.f32.f16.f16.f32 "
                 "{%0,%1,%2,%3}, {%4,%5,%6,%7}, {%8,%9}, {%0,%1,%2,%3};"
                 : "+f"(c[0]), "+f"(c[1]), "+f"(c[2]), "+f"(c[3])
                 : "r"(a[0]), "r"(a[1]), "r"(a[2]), "r"(a[3]), "r"(b[0]), "r"(b[1]));
}
__device__ __forceinline__ float gelu_tanh(float x) {
    float u = 0.7978845608028654f * (x + 0.044715f * x * x * x);
    u = fminf(fmaxf(u, -15.0f), 15.0f);
    float e = __expf(2.0f * u);
    return x * e / (e + 1.0f);
}
__device__ __forceinline__ uint32_t pkh2(float a, float b) {
    __half2 t = __floats2half2_rn(a, b);
    return *(uint32_t*)&t;
}

// ---------------- HMMA GEMM: 4-stage cp.async ring, NT=128, occ 2 ----------------
// MODE 0: QKV (+bias; q/k -> gb_qkv, v -> gb_vT transposed)
// MODE 1: outproj (+bias+res, f32 out)
// MODE 4: MoE1 (gather rows, +b1, gelu, f16 out)   MODE 5: MoE2 (+b2, f16 out)
#define STAGES 4
template <int MODE, int NT>
__global__ void __launch_bounds__(256, 2) hgemm(
    const __half* __restrict__ A, const __half* __restrict__ B, void* Cv,
    int M, int N, int K, int lda, int ldb, int ldc,
    const float* __restrict__ bias, const float* __restrict__ res,
    const int* __restrict__ gtok, const int* __restrict__ offs) {
    extern __shared__ __align__(128) char dsm[];
    constexpr uint32_t AST = 128 * 40 * 2;
    constexpr uint32_t BST = NT * 40 * 2;

    int tid = threadIdx.x, wid = tid >> 5, lid = tid & 31;
    int z = blockIdx.z;
    const __half* Ab = A;
    const __half* Bb = B;
    float* Cf = (float*)Cv;
    __half* Cb = (__half*)Cv;
    const float* biasb = bias;
    int r0 = 0, r1 = M;
    if (MODE == 4 || MODE == 5) {
        r0 = offs[z]; r1 = offs[z + 1];
        Bb = B + (size_t)z * (size_t)N * K;
        biasb = bias + (size_t)z * N;
    }
    int rowBase = r0 + blockIdx.y * 128;
    if (rowBase >= r1) return;
    int n0 = blockIdx.x * NT;

    constexpr int WN = NT / 4;
    constexpr int NTILES = WN / 8;
    int wm = (wid >> 2) * 64;
    int wn = (wid & 3) * WN;

    uint32_t uAs = s2u(dsm);
    uint32_t uBs = uAs + STAGES * AST;

    int aRowL = wm + (lid & 15);
    int aColL = (lid >> 4) * 8;
    int bRowL = wn + ((lid >> 4) << 3) + (lid & 7);
    int bColL = ((lid >> 3) & 1) * 8;

    float acc[4][NTILES][4];
#pragma unroll
    for (int i = 0; i < 4; i++)
#pragma unroll
        for (int j = 0; j < NTILES; j++)
#pragma unroll
            for (int q = 0; q < 4; q++) acc[i][j][q] = 0.f;

    int ldRow = tid >> 2, ldCh = tid & 3;
    int gr0 = rowBase + ldRow;       if (gr0 > r1 - 1) gr0 = r1 - 1;
    int gr1 = rowBase + ldRow + 64;  if (gr1 > r1 - 1) gr1 = r1 - 1;
    const __half* aSrc0;
    const __half* aSrc1;
    if (MODE == 4) { aSrc0 = Ab + (size_t)gtok[gr0] * lda; aSrc1 = Ab + (size_t)gtok[gr1] * lda; }
    else           { aSrc0 = Ab + (size_t)gr0 * lda;        aSrc1 = Ab + (size_t)gr1 * lda; }

    auto loadStage = [&](int st, int c) {
        int kt = c * 32;
        cpasync16(uAs + st * AST + ldRow * 80 + ldCh * 16,        aSrc0 + kt + ldCh * 8);
        cpasync16(uAs + st * AST + (ldRow + 64) * 80 + ldCh * 16, aSrc1 + kt + ldCh * 8);
#pragma unroll
        for (int i = 0; i < NT / 64; i++) {
            int idx = tid + i * 256;
            int row = idx >> 2, ch = idx & 3;
            cpasync16(uBs + st * BST + row * 80 + ch * 16,
                      Bb + (size_t)(n0 + row) * ldb + kt + ch * 8);
        }
    };

    int nk = K / 32;
    loadStage(0, 0); CP_COMMIT();
    loadStage(1, 1); CP_COMMIT();
    loadStage(2, 2); CP_COMMIT();

    for (int c = 0; c < nk; c++) {
        CP_WAIT(2);
        __syncthreads();
        if (c + 3 < nk) loadStage((c + 3) & (STAGES - 1), c + 3);
        CP_COMMIT();   // always commit — keeps wait invariant at the tail
        int st = c & (STAGES - 1);
        uint32_t aBase = uAs + st * AST;
        uint32_t bBase = uBs + st * BST;
#pragma unroll
        for (int ks = 0; ks < 2; ks++) {
            uint32_t afr[4][4];
#pragma unroll
            for (int mt = 0; mt < 4; mt++)
                ldsm4(afr[mt], aBase + (aRowL + mt * 16) * 80 + (ks * 16 + aColL) * 2);
#pragma unroll
            for (int nb = 0; nb < NTILES / 2; nb++) {
                uint32_t bfr[4];
                ldsm4(bfr, bBase + (bRowL + nb * 16) * 80 + (ks * 16 + bColL) * 2);
#pragma unroll
                for (int mt = 0; mt < 4; mt++) {
                    mma16816(acc[mt][2 * nb],     afr[mt], &bfr[0]);
                    mma16816(acc[mt][2 * nb + 1], afr[mt], &bfr[2]);
                }
            }
        }
    }

#pragma unroll
    for (int mt = 0; mt < 4; mt++) {
#pragma unroll
        for (int h = 0; h < 2; h++) {
            int row = rowBase + wm + mt * 16 + h * 8 + (lid >> 2);
            if (row >= r1) continue;
#pragma unroll
            for (int nt = 0; nt < NTILES; nt++) {
                float v0 = acc[mt][nt][2 * h], v1 = acc[mt][nt][2 * h + 1];
                int cc = n0 + wn + nt * 8 + 2 * (lid & 3);
                if (MODE == 0) { v0 += bias[cc]; v1 += bias[cc + 1]; }
                if (MODE == 1) {
                    float2 rr = *(const float2*)(res + (size_t)row * ldc + cc);
                    v0 += bias[cc] + rr.x; v1 += bias[cc + 1] + rr.y;
                }
                if (MODE == 4) {
                    v0 = gelu_tanh(v0 + biasb[cc]);
                    v1 = gelu_tanh(v1 + biasb[cc + 1]);
                }
                if (MODE == 5) { v0 += biasb[cc]; v1 += biasb[cc + 1]; }
                if (MODE == 1) {
                    *(float2*)(Cf + (size_t)row * ldc + cc) = make_float2(v0, v1);
                } else if (MODE == 0 && cc >= 2 * HID) {
                    // V-section: write straight into per-head V^T (fused vtrans)
                    int d = cc - 2 * HID;
                    int hh = d >> 6, dd = d & 63;
                    int bb = row >> 11, ss = row & 2047;
                    uint32_t pk = pkh2(v0, v1);
                    __half2 pr = *(__half2*)&pk;
                    __half* vb = gb_vT + ((size_t)(bb * NHEAD + hh) * 64 + dd) * SEQ + ss;
                    vb[0]   = __low2half(pr);
                    vb[SEQ] = __high2half(pr);
                } else {
                    *(uint32_t*)(Cb + (size_t)row * ldc + cc) = pkh2(v0, v1);
                }
            }
        }
    }
}

// ---------------- fused flash attention ----------------
__global__ void __launch_bounds__(256, 1) flash_k(const __half* __restrict__ qkv,
                                                  const __half* __restrict__ vT,
                                                  __half* __restrict__ ao) {
    extern __shared__ char dyn[];
    constexpr uint32_t QBYTES = 128 * 72 * 2;
    constexpr uint32_t KST    = 128 * 72 * 2;
    constexpr uint32_t VST    = 64 * 136 * 2;
    char* sQ = dyn;
    char* sK = dyn + QBYTES;
    char* sV = dyn + QBYTES + 2 * KST;

    int tid = threadIdx.x, wid = tid >> 5, lid = tid & 31;
    int qt = blockIdx.x, bh = blockIdx.y;
    int b = bh >> 4, h = bh & 15;
    int q0 = qt * 128;
    const __half* Qg = qkv + (size_t)b * SEQ * 3 * HID + h * 64;
    const __half* Kg = qkv + (size_t)b * SEQ * 3 * HID + HID + h * 64;
    const __half* Vt = vT + (size_t)bh * 64 * SEQ;

    uint32_t uQ = s2u(sQ), uK = s2u(sK), uV = s2u(sV);

#pragma unroll
    for (int i = 0; i < 4; i++) {
        int idx = tid + i * 256;
        int row = idx >> 3, ch = idx & 7;
        cpasync16(uQ + row * 144 + ch * 16, Qg + (size_t)(q0 + row) * 3 * HID + ch * 8);
    }
    auto loadKV = [&](int st, int kt) {
#pragma unroll
        for (int i = 0; i < 4; i++) {
            int idx = tid + i * 256;
            int row = idx >> 3, ch = idx & 7;
            cpasync16(uK + st * KST + row * 144 + ch * 16,
                      Kg + (size_t)(kt * 128 + row) * 3 * HID + ch * 8);
        }
#pragma unroll
        for (int i = 0; i < 4; i++) {
            int idx = tid + i * 256;
            int row = idx >> 4, ch = idx & 15;
            cpasync16(uV + st * VST + row * 272 + ch * 16,
                      Vt + (size_t)row * SEQ + kt * 128 + ch * 8);
        }
    };
    loadKV(0, 0);
    CP_COMMIT();

    float oacc[8][4];
#pragma unroll
    for (int j = 0; j < 8; j++)
#pragma unroll
        for (int q = 0; q < 4; q++) oacc[j][q] = 0.f;
    float m0 = -1e30f, m1 = -1e30f, l0 = 0.f, l1 = 0.f;

    int aRowL = wid * 16 + (lid & 15);
    int aColL = (lid >> 4) * 8;
    int bRowL = ((lid >> 4) << 3) + (lid & 7);
    int bColL = ((lid >> 3) & 1) * 8;

    for (int kt = 0; kt < SEQ / 128; kt++) {
        if (kt + 1 < SEQ / 128) { loadKV((kt + 1) & 1, kt + 1); CP_COMMIT(); CP_WAIT(1); }
        else CP_WAIT(0);
        __syncthreads();
        int st = kt & 1;
        uint32_t kBase = uK + st * KST;
        uint32_t vBase = uV + st * VST;

        float sacc[16][4];
#pragma unroll
        for (int t = 0; t < 16; t++)
#pragma unroll
            for (int q = 0; q < 4; q++) sacc[t][q] = 0.f;

#pragma unroll
        for (int ks = 0; ks < 4; ks++) {
            uint32_t afr[4];
            ldsm4(afr, uQ + aRowL * 144 + (ks * 16 + aColL) * 2);
#pragma unroll
            for (int nb = 0; nb < 8; nb++) {
                uint32_t bfr[4];
                ldsm4(bfr, kBase + (nb * 16 + bRowL) * 144 + (ks * 16 + bColL) * 2);
                mma16816(sacc[2 * nb],     afr, &bfr[0]);
                mma16816(sacc[2 * nb + 1], afr, &bfr[2]);
            }
        }

        float tm0 = -1e30f, tm1 = -1e30f;
#pragma unroll
        for (int t = 0; t < 16; t++) {
            sacc[t][0] *= 0.125f; sacc[t][1] *= 0.125f;
            sacc[t][2] *= 0.125f; sacc[t][3] *= 0.125f;
            tm0 = fmaxf(tm0, fmaxf(sacc[t][0], sacc[t][1]));
            tm1 = fmaxf(tm1, fmaxf(sacc[t][2], sacc[t][3]));
        }
        tm0 = fmaxf(tm0, __shfl_xor_sync(0xffffffffu, tm0, 1));
        tm0 = fmaxf(tm0, __shfl_xor_sync(0xffffffffu, tm0, 2));
        tm1 = fmaxf(tm1, __shfl_xor_sync(0xffffffffu, tm1, 1));
        tm1 = fmaxf(tm1, __shfl_xor_sync(0xffffffffu, tm1, 2));
        float nm0 = fmaxf(m0, tm0), nm1 = fmaxf(m1, tm1);
        float f0 = __expf(m0 - nm0), f1 = __expf(m1 - nm1);
        m0 = nm0; m1 = nm1;
        float rs0 = 0.f, rs1 = 0.f;
#pragma unroll
        for (int t = 0; t < 16; t++) {
            sacc[t][0] = __expf(sacc[t][0] - nm0);
            sacc[t][1] = __expf(sacc[t][1] - nm0);
            sacc[t][2] = __expf(sacc[t][2] - nm1);
            sacc[t][3] = __expf(sacc[t][3] - nm1);
            rs0 += sacc[t][0] + sacc[t][1];
            rs1 += sacc[t][2] + sacc[t][3];
        }
        rs0 += __shfl_xor_sync(0xffffffffu, rs0, 1);
        rs0 += __shfl_xor_sync(0xffffffffu, rs0, 2);
        rs1 += __shfl_xor_sync(0xffffffffu, rs1, 1);
        rs1 += __shfl_xor_sync(0xffffffffu, rs1, 2);
        l0 = l0 * f0 + rs0;
        l1 = l1 * f1 + rs1;
#pragma unroll
        for (int j = 0; j < 8; j++) {
            oacc[j][0] *= f0; oacc[j][1] *= f0;
            oacc[j][2] *= f1; oacc[j][3] *= f1;
        }

#pragma unroll
        for (int ks = 0; ks < 8; ks++) {
            uint32_t pa[4];
            pa[0] = pkh2(sacc[2 * ks][0],     sacc[2 * ks][1]);
            pa[1] = pkh2(sacc[2 * ks][2],     sacc[2 * ks][3]);
            pa[2] = pkh2(sacc[2 * ks + 1][0], sacc[2 * ks + 1][1]);
            pa[3] = pkh2(sacc[2 * ks + 1][2], sacc[2 * ks + 1][3]);
#pragma unroll
            for (int nb = 0; nb < 4; nb++) {
                uint32_t bfr[4];
                ldsm4(bfr, vBase + (nb * 16 + bRowL) * 272 + (ks * 16 + bColL) * 2);
                mma16816(oacc[2 * nb],     pa, &bfr[0]);
                mma16816(oacc[2 * nb + 1], pa, &bfr[2]);
            }
        }
        __syncthreads();
    }

    float i0 = 1.0f / l0, i1 = 1.0f / l1;
    int row = q0 + wid * 16 + (lid >> 2);
    __half* d0 = ao + ((size_t)b * SEQ + row) * HID + h * 64;
    __half* d1 = ao + ((size_t)b * SEQ + row + 8) * HID + h * 64;
#pragma unroll
    for (int j = 0; j < 8; j++) {
        int cc = j * 8 + (lid & 3) * 2;
        *(uint32_t*)(d0 + cc) = pkh2(oacc[j][0] * i0, oacc[j][1] * i0);
        *(uint32_t*)(d1 + cc) = pkh2(oacc[j][2] * i1, oacc[j][3] * i1);
    }
}

// ---------------- support kernels ----------------
__global__ void __launch_bounds__(256) f2h_k(const float* __restrict__ in, __half* __restrict__ outp, int n4) {
    int i = blockIdx.x * 256 + threadIdx.x;
    if (i >= n4) return;
    float4 v = ((const float4*)in)[i];
    ((uint2*)outp)[i] = make_uint2(pkh2(v.x, v.y), pkh2(v.z, v.w));
}

__global__ void tconv_k(const float* __restrict__ in, __half* __restrict__ outp, int R, int C) {
    __shared__ float t[32][33];
    in += (size_t)blockIdx.z * R * C;
    outp += (size_t)blockIdx.z * R * C;
    int x = blockIdx.x * 32 + threadIdx.x;
    int y0 = blockIdx.y * 32;
#pragma unroll
    for (int j = 0; j < 32; j += 8)
        t[threadIdx.y + j][threadIdx.x] = in[(size_t)(y0 + threadIdx.y + j) * C + x];
    __syncthreads();
    int ox = y0 + threadIdx.x;
    int oy0 = blockIdx.x * 32;
#pragma unroll
    for (int j = 0; j < 32; j += 8)
        outp[(size_t)(oy0 + threadIdx.y + j) * R + ox] = __float2half_rn(t[threadIdx.x][threadIdx.y + j]);
}

template <bool BOTH>
__global__ void __launch_bounds__(256) ln_k(const float* __restrict__ x, const float* __restrict__ g,
                                            const float* __restrict__ bta,
                                            __half* __restrict__ ob, float* __restrict__ of) {
    __shared__ float red[16], fin[2];
    int tid = threadIdx.x;
    size_t row = blockIdx.x;
    float4 v = ((const float4*)(x + row * HID))[tid];
    float s = v.x + v.y + v.z + v.w;
    float q = v.x * v.x + v.y * v.y + v.z * v.z + v.w * v.w;
#pragma unroll
    for (int o = 16; o; o >>= 1) {
        s += __shfl_xor_sync(0xffffffffu, s, o);
        q += __shfl_xor_sync(0xffffffffu, q, o);
    }
    if ((tid & 31) == 0) { red[tid >> 5] = s; red[8 + (tid >> 5)] = q; }
    __syncthreads();
    if (tid < 8) {
        s = red[tid]; q = red[8 + tid];
#pragma unroll
        for (int o = 4; o; o >>= 1) {
            s += __shfl_xor_sync(0xffu, s, o);
            q += __shfl_xor_sync(0xffu, q, o);
        }
        if (tid == 0) {
            float mu = s * (1.0f / HID);
            fin[0] = mu;
            fin[1] = rsqrtf(q * (1.0f / HID) - mu * mu + 1e-5f);
        }
    }
    __syncthreads();
    float mu = fin[0], rstd = fin[1];
    float4 gv = ((const float4*)g)[tid];
    float4 bv = ((const float4*)bta)[tid];
    float4 o;
    o.x = (v.x - mu) * rstd * gv.x + bv.x;
    o.y = (v.y - mu) * rstd * gv.y + bv.y;
    o.z = (v.z - mu) * rstd * gv.z + bv.z;
    o.w = (v.w - mu) * rstd * gv.w + bv.w;
    ((uint2*)(ob + row * HID))[tid] = make_uint2(pkh2(o.x, o.y), pkh2(o.z, o.w));
    if (BOTH) ((float4*)(of + row * HID))[tid] = o;
}

__global__ void __launch_bounds__(256) gate_k(const float* __restrict__ Wg) {
    int warp = (blockIdx.x * 256 + threadIdx.x) >> 5;
    int lane = threadIdx.x & 31;
    if (warp >= TOK) return;
    const float* xr = g_h2f + (size_t)warp * HID;
    float acc[8] = {0, 0, 0, 0, 0, 0, 0, 0};
    for (int hh = lane; hh < HID; hh += 32) {
        float xv = xr[hh];
        float4 w0 = *(const float4*)(Wg + hh * 8);
        float4 w1 = *(const float4*)(Wg + hh * 8 + 4);
        acc[0] += xv * w0.x; acc[1] += xv * w0.y; acc[2] += xv * w0.z; acc[3] += xv * w0.w;
        acc[4] += xv * w1.x; acc[5] += xv * w1.y; acc[6] += xv * w1.z; acc[7] += xv * w1.w;
    }
#pragma unroll
    for (int o = 16; o; o >>= 1)
#pragma unroll
        for (int e = 0; e < 8; e++) acc[e] += __shfl_xor_sync(0xffffffffu, acc[e], o);
    if (lane == 0) {
        int i0 = 0; float v0 = acc[0];
#pragma unroll
        for (int e = 1; e < 8; e++) if (acc[e] > v0) { v0 = acc[e]; i0 = e; }
        int i1 = -1; float v1 = -3.4e38f;
#pragma unroll
        for (int e = 0; e < 8; e++) if (e != i0 && acc[e] > v1) { v1 = acc[e]; i1 = e; }
        float w0 = 1.0f / (1.0f + __expf(v1 - v0));
        g_topi[2 * warp] = i0; g_topi[2 * warp + 1] = i1;
        g_topw[2 * warp] = w0; g_topw[2 * warp + 1] = 1.0f - w0;
        atomicAdd(&g_cnt[i0], 1);
        atomicAdd(&g_cnt[i1], 1);
    }
}

// merged scan + scatter (single block)
__global__ void __launch_bounds__(1024) route_k() {
    if (threadIdx.x == 0) {
        g_offs[0] = 0;
        for (int e = 0; e < NEXP; e++) g_offs[e + 1] = g_offs[e] + g_cnt[e];
    }
    __syncthreads();
    for (int idx = threadIdx.x; idx < TOK * 2; idx += 1024) {
        int e = g_topi[idx];
        int pos = atomicAdd(&g_cur[e], 1);
        int slot = g_offs[e] + pos;
        g_slottok[slot] = idx >> 1;
        g_slotof[idx] = slot;
    }
}

// combine with f16 Y2
__global__ void __launch_bounds__(256) combine_k(float* __restrict__ outp) {
    int t = blockIdx.x;
    int j = threadIdx.x;
    float w0 = g_topw[2 * t], w1 = g_topw[2 * t + 1];
    size_t s0 = g_slotof[2 * t], s1 = g_slotof[2 * t + 1];
    float4 r = ((const float4*)(g_xattn + (size_t)t * HID))[j];
    uint2 y0r = ((const uint2*)(gb_Y2 + s0 * HID))[j];
    uint2 y1r = ((const uint2*)(gb_Y2 + s1 * HID))[j];
    float2 y0a = __half22float2(*(__half2*)&y0r.x);
    float2 y0b = __half22float2(*(__half2*)&y0r.y);
    float2 y1a = __half22float2(*(__half2*)&y1r.x);
    float2 y1b = __half22float2(*(__half2*)&y1r.y);
    r.x += w0 * y0a.x + w1 * y1a.x;
    r.y += w0 * y0a.y + w1 * y1a.y;
    r.z += w0 * y0b.x + w1 * y1b.x;
    r.w += w0 * y0b.y + w1 * y1b.y;
    ((float4*)(outp + (size_t)t * HID))[j] = r;
}

#define SYM(p, s) void* p; cudaGetSymbolAddress(&p, s)

extern "C" void kernel_launch(void* const* d_in, const int* in_sizes, int n_in,
                              void* d_out, int out_size) {
    const float* x     = (const float*)d_in[0];
    const float* ln1_g = (const float*)d_in[1];
    const float* ln1_b = (const float*)d_in[2];
    const float* qkv_w = (const float*)d_in[3];
    const float* qkv_b = (const float*)d_in[4];
    const float* out_w = (const float*)d_in[5];
    const float* out_b = (const float*)d_in[6];
    const float* ln2_g = (const float*)d_in[7];
    const float* ln2_b = (const float*)d_in[8];
    const float* Wg    = (const float*)d_in[9];
    const float* W1    = (const float*)d_in[10];
    const float* b1    = (const float*)d_in[11];
    const float* W2    = (const float*)d_in[12];
    const float* b2    = (const float*)d_in[13];
    float* outp = (float*)d_out;

    SYM(p_hln, gb_hln);   SYM(p_qkvw, gb_qkvw); SYM(p_outw, gb_outw);
    SYM(p_w1t, gb_w1t);   SYM(p_w2t, gb_w2t);   SYM(p_qkv, gb_qkv);
    SYM(p_vT, gb_vT);     SYM(p_ao, gb_ao);     SYM(p_h2b, gb_h2);
    SYM(p_H1, gb_H1);     SYM(p_xattn, g_xattn); SYM(p_h2f, g_h2f);
    SYM(p_Y2, gb_Y2);     SYM(p_cnt, g_cnt);    SYM(p_cur, g_cur);
    SYM(p_slottok, g_slottok); SYM(p_offs, g_offs);

    constexpr int GEMM_SMEM = STAGES * (128 + 128) * 40 * 2;  // 81920
    cudaFuncSetAttribute(hgemm<0, 128>, cudaFuncAttributeMaxDynamicSharedMemorySize, GEMM_SMEM);
    cudaFuncSetAttribute(hgemm<1, 128>, cudaFuncAttributeMaxDynamicSharedMemorySize, GEMM_SMEM);
    cudaFuncSetAttribute(hgemm<4, 128>, cudaFuncAttributeMaxDynamicSharedMemorySize, GEMM_SMEM);
    cudaFuncSetAttribute(hgemm<5, 128>, cudaFuncAttributeMaxDynamicSharedMemorySize, GEMM_SMEM);
    constexpr int FLASH_SMEM = (128 * 72 * 2) * 3 + (64 * 136 * 2) * 2;  // 90112
    cudaFuncSetAttribute(flash_k, cudaFuncAttributeMaxDynamicSharedMemorySize, FLASH_SMEM);

    cudaStream_t s2;
    cudaStreamCreateWithFlags(&s2, cudaStreamNonBlocking);
    cudaEvent_t evFork, evJoin;
    cudaEventCreateWithFlags(&evFork, cudaEventDisableTiming);
    cudaEventCreateWithFlags(&evJoin, cudaEventDisableTiming);

    cudaEventRecord(evFork, 0);
    cudaStreamWaitEvent(s2, evFork, 0);

    dim3 tb(32, 8);
    // side stream: MoE weight transposes, out_w convert, routing counters
    tconv_k<<<dim3(FDIM / 32, HID / 32, NEXP), tb, 0, s2>>>(W1, (__half*)p_w1t, HID, FDIM);
    tconv_k<<<dim3(HID / 32, FDIM / 32, NEXP), tb, 0, s2>>>(W2, (__half*)p_w2t, FDIM, HID);
    f2h_k<<<(HID * HID / 4 + 255) / 256, 256, 0, s2>>>(out_w, (__half*)p_outw, HID * HID / 4);
    cudaMemsetAsync(p_cnt, 0, NEXP * sizeof(int), s2);
    cudaMemsetAsync(p_cur, 0, NEXP * sizeof(int), s2);
    cudaEventRecord(evJoin, s2);

    // main stream: attention phase
    f2h_k<<<(3 * HID * HID / 4 + 255) / 256, 256>>>(qkv_w, (__half*)p_qkvw, 3 * HID * HID / 4);
    ln_k<false><<<TOK, 256>>>(x, ln1_g, ln1_b, (__half*)p_hln, nullptr);

    // QKV GEMM: q/k -> gb_qkv, v -> gb_vT (fused transpose in epilogue)
    hgemm<0, 128><<<dim3(3 * HID / 128, TOK / 128, 1), 256, GEMM_SMEM>>>(
        (const __half*)p_hln, (const __half*)p_qkvw, p_qkv,
        TOK, 3 * HID, HID, HID, HID, 3 * HID, qkv_b, nullptr, nullptr, nullptr);

    flash_k<<<dim3(SEQ / 128, 2 * NHEAD), 256, FLASH_SMEM>>>(
        (const __half*)p_qkv, (const __half*)p_vT, (__half*)p_ao);

    cudaStreamWaitEvent(0, evJoin, 0);

    hgemm<1, 128><<<dim3(HID / 128, TOK / 128, 1), 256, GEMM_SMEM>>>(
        (const __half*)p_ao, (const __half*)p_outw, p_xattn,
        TOK, HID, HID, HID, HID, HID, out_b, x, nullptr, nullptr);

    ln_k<true><<<TOK, 256>>>((const float*)p_xattn, ln2_g, ln2_b,
                             (__half*)p_h2b, (float*)p_h2f);

    gate_k<<<TOK / 8, 256>>>(Wg);
    route_k<<<1, 1024>>>();

    hgemm<4, 128><<<dim3(FDIM / 128, NSLOT / 128, NEXP), 256, GEMM_SMEM>>>(
        (const __half*)p_h2b, (const __half*)p_w1t, p_H1,
        0, FDIM, HID, HID, HID, FDIM, b1, nullptr, (const int*)p_slottok, (const int*)p_offs);

    hgemm<5, 128><<<dim3(HID / 128, NSLOT / 128, NEXP), 256, GEMM_SMEM>>>(
        (const __half*)p_H1, (const __half*)p_w2t, p_Y2,
        0, HID, FDIM, FDIM, FDIM, HID, b2, nullptr, nullptr, (const int*)p_offs);

    combine_k<<<TOK, 256>>>(outp);

    cudaStreamDestroy(s2);
    cudaEventDestroy(evFork);
    cudaEventDestroy(evJoin);
}

// round 14
// speedup vs baseline: 1.0561x; 1.0521x over previous
#include <cuda_runtime.h>
#include <cuda_fp16.h>
#include <cstdint>
#include <cstddef>

#define TOK   4096
#define SEQ   2048
#define HID   1024
#define NHEAD 16
#define NEXP  8
#define FDIM  4096
#define NSLOT 8192

// ---------------- scratch ----------------
__device__ __align__(128) __half gb_hln [(size_t)TOK * HID];
__device__ __align__(128) __half gb_qkvw[(size_t)3 * HID * HID];
__device__ __align__(128) __half gb_outw[(size_t)HID * HID];
__device__ __align__(128) __half gb_w1t [(size_t)NEXP * FDIM * HID];
__device__ __align__(128) __half gb_w2t [(size_t)NEXP * HID * FDIM];
__device__ __align__(128) __half gb_qkv [(size_t)TOK * 3 * HID];
__device__ __align__(128) __half gb_vT  [(size_t)2 * NHEAD * 64 * SEQ];
__device__ __align__(128) __half gb_ao  [(size_t)TOK * HID];
__device__ __align__(128) __half gb_h2  [(size_t)TOK * HID];
__device__ __align__(128) __half gb_H1  [(size_t)NSLOT * FDIM];
__device__ float g_xattn[(size_t)TOK * HID];
__device__ float g_h2f  [(size_t)TOK * HID];
__device__ float g_Y2   [(size_t)NSLOT * HID];
__device__ int   g_topi [TOK * 2];
__device__ float g_topw [TOK * 2];
__device__ int   g_cnt  [NEXP];
__device__ int   g_offs [NEXP + 1];
__device__ int   g_cur  [NEXP];
__device__ int   g_slottok[NSLOT];
__device__ int   g_slotof [TOK * 2];

// ---------------- PTX helpers ----------------
__device__ __forceinline__ uint32_t s2u(const void* p) {
    uint32_t a;
    asm("{ .reg .u64 t; cvta.to.shared.u64 t, %1; cvt.u32.u64 %0, t; }" : "=r"(a) : "l"(p));
    return a;
}
__device__ __forceinline__ void cpasync16(uint32_t saddr, const void* g) {
    asm volatile("cp.async.cg.shared.global [%0], [%1], 16;" :: "r"(saddr), "l"(g));
}
#define CP_COMMIT() asm volatile("cp.async.commit_group;" ::: "memory")
#define CP_WAIT(n)  asm volatile("cp.async.wait_group %0;" :: "n"(n) : "memory")

__device__ __forceinline__ void ldsm4(uint32_t* r, uint32_t addr) {
    asm volatile("ldmatrix.sync.aligned.m8n8.x4.shared.b16 {%0,%1,%2,%3}, [%4];"
                 : "=r"(r[0]), "=r"(r[1]), "=r"(r[2]), "=r"(r[3]) : "r"(addr));
}
__device__ __forceinline__ void mma16816(float* c, const uint32_t* a, const uint32_t* b) {
    asm volatile("mma.sync.aligned.m16n8k16.row.col.f32.f16.f16.f32 "
                 "{%0,%1,%2,%3}, {%4,%5,%6,%7}, {%8,%9}, {%0,%1,%2,%3};"
                 : "+f"(c[0]), "+f"(c[1]), "+f"(c[2]), "+f"(c[3])
                 : "r"(a[0]), "r"(a[1]), "r"(a[2]), "r"(a[3]), "r"(b[0]), "r"(b[1]));
}
__device__ __forceinline__ float gelu_tanh(float x) {
    float u = 0.7978845608028654f * (x + 0.044715f * x * x * x);
    u = fminf(fmaxf(u, -15.0f), 15.0f);
    float e = __expf(2.0f * u);
    return x * e / (e + 1.0f);
}
__device__ __forceinline__ uint32_t pkh2(float a, float b) {
    __half2 t = __floats2half2_rn(a, b);
    return *(uint32_t*)&t;
}

// ---------------- HMMA GEMM: BK=64 chunks, 3-stage cp.async ring ----------------
// pitch 72 halves (144B) per row — conflict-free for ldsm (rows on disjoint bank quads).
// Invariant: one commit per iteration (empty past tail); CP_WAIT(1) at iter c
// proves chunk c resident; stage (c+2)%3 was last read at iter c-1, protected
// by iter-c's barrier.
// MODE 0: QKV (+bias; q/k -> gb_qkv, v -> gb_vT transposed)
// MODE 1: outproj (+bias+res, f32 out)
// MODE 4: MoE1 (gather rows, +b1, gelu, f16 out)   MODE 5: MoE2 (+b2, f32 out)
#define STAGES3 3
template <int MODE, int NT>
__global__ void __launch_bounds__(256, 2) hgemm(
    const __half* __restrict__ A, const __half* __restrict__ B, void* Cv,
    int M, int N, int K, int lda, int ldb, int ldc,
    const float* __restrict__ bias, const float* __restrict__ res,
    const int* __restrict__ gtok, const int* __restrict__ offs) {
    extern __shared__ __align__(128) char dsm[];
    constexpr uint32_t AST = 128 * 144;     // 128 rows x 72 halves
    constexpr uint32_t BST = NT * 144;

    int tid = threadIdx.x, wid = tid >> 5, lid = tid & 31;
    int z = blockIdx.z;
    const __half* Ab = A;
    const __half* Bb = B;
    float* Cf = (float*)Cv;
    __half* Cb = (__half*)Cv;
    const float* biasb = bias;
    int r0 = 0, r1 = M;
    if (MODE == 4 || MODE == 5) {
        r0 = offs[z]; r1 = offs[z + 1];
        Bb = B + (size_t)z * (size_t)N * K;
        biasb = bias + (size_t)z * N;
    }
    int rowBase = r0 + blockIdx.y * 128;
    if (rowBase >= r1) return;
    int n0 = blockIdx.x * NT;

    constexpr int WN = NT / 4;
    constexpr int NTILES = WN / 8;
    int wm = (wid >> 2) * 64;
    int wn = (wid & 3) * WN;

    uint32_t uAs = s2u(dsm);
    uint32_t uBs = uAs + STAGES3 * AST;

    int aRowL = wm + (lid & 15);
    int aColL = (lid >> 4) * 8;
    int bRowL = wn + ((lid >> 4) << 3) + (lid & 7);
    int bColL = ((lid >> 3) & 1) * 8;

    float acc[4][NTILES][4];
#pragma unroll
    for (int i = 0; i < 4; i++)
#pragma unroll
        for (int j = 0; j < NTILES; j++)
#pragma unroll
            for (int q = 0; q < 4; q++) acc[i][j][q] = 0.f;

    // per-thread load lanes: 8 chunks of 16B per 64-half row
    int ldRow = tid >> 3, ldCh = tid & 7;
    const __half* aSrc[4];
#pragma unroll
    for (int i = 0; i < 4; i++) {
        int gr = rowBase + ldRow + i * 32;
        if (gr > r1 - 1) gr = r1 - 1;
        aSrc[i] = Ab + (size_t)((MODE == 4) ? gtok[gr] : gr) * lda;
    }

    auto loadStage = [&](int st, int c) {
        int kt = c * 64;
#pragma unroll
        for (int i = 0; i < 4; i++)
            cpasync16(uAs + st * AST + (ldRow + i * 32) * 144 + ldCh * 16,
                      aSrc[i] + kt + ldCh * 8);
#pragma unroll
        for (int i = 0; i < NT / 32; i++) {
            int row = ldRow + i * 32;
            cpasync16(uBs + st * BST + row * 144 + ldCh * 16,
                      Bb + (size_t)(n0 + row) * ldb + kt + ldCh * 8);
        }
    };

    int nk = K / 64;
    loadStage(0, 0); CP_COMMIT();
    loadStage(1, 1); CP_COMMIT();

    int cSt = 0, ldSt = 2;
    for (int c = 0; c < nk; c++) {
        CP_WAIT(1);
        __syncthreads();
        if (c + 2 < nk) loadStage(ldSt, c + 2);
        CP_COMMIT();   // always commit — keeps the wait invariant at the tail
        uint32_t aBase = uAs + cSt * AST;
        uint32_t bBase = uBs + cSt * BST;
#pragma unroll
        for (int ks = 0; ks < 4; ks++) {
            uint32_t afr[4][4];
#pragma unroll
            for (int mt = 0; mt < 4; mt++)
                ldsm4(afr[mt], aBase + (aRowL + mt * 16) * 144 + (ks * 16 + aColL) * 2);
#pragma unroll
            for (int nb = 0; nb < NTILES / 2; nb++) {
                uint32_t bfr[4];
                ldsm4(bfr, bBase + (bRowL + nb * 16) * 144 + (ks * 16 + bColL) * 2);
#pragma unroll
                for (int mt = 0; mt < 4; mt++) {
                    mma16816(acc[mt][2 * nb],     afr[mt], &bfr[0]);
                    mma16816(acc[mt][2 * nb + 1], afr[mt], &bfr[2]);
                }
            }
        }
        cSt  = (cSt  == 2) ? 0 : cSt + 1;
        ldSt = (ldSt == 2) ? 0 : ldSt + 1;
    }

#pragma unroll
    for (int mt = 0; mt < 4; mt++) {
#pragma unroll
        for (int h = 0; h < 2; h++) {
            int row = rowBase + wm + mt * 16 + h * 8 + (lid >> 2);
            if (row >= r1) continue;
#pragma unroll
            for (int nt = 0; nt < NTILES; nt++) {
                float v0 = acc[mt][nt][2 * h], v1 = acc[mt][nt][2 * h + 1];
                int cc = n0 + wn + nt * 8 + 2 * (lid & 3);
                if (MODE == 0) { v0 += bias[cc]; v1 += bias[cc + 1]; }
                if (MODE == 1) {
                    float2 rr = *(const float2*)(res + (size_t)row * ldc + cc);
                    v0 += bias[cc] + rr.x; v1 += bias[cc + 1] + rr.y;
                }
                if (MODE == 4) {
                    v0 = gelu_tanh(v0 + biasb[cc]);
                    v1 = gelu_tanh(v1 + biasb[cc + 1]);
                }
                if (MODE == 5) { v0 += biasb[cc]; v1 += biasb[cc + 1]; }
                if (MODE == 1 || MODE == 5) {
                    *(float2*)(Cf + (size_t)row * ldc + cc) = make_float2(v0, v1);
                } else if (MODE == 0 && cc >= 2 * HID) {
                    // V-section: write straight into per-head V^T (fused vtrans)
                    int d = cc - 2 * HID;
                    int hh = d >> 6, dd = d & 63;
                    int bb = row >> 11, ss = row & 2047;
                    uint32_t pk = pkh2(v0, v1);
                    __half2 pr = *(__half2*)&pk;
                    __half* vb = gb_vT + ((size_t)(bb * NHEAD + hh) * 64 + dd) * SEQ + ss;
                    vb[0]   = __low2half(pr);
                    vb[SEQ] = __high2half(pr);
                } else {
                    *(uint32_t*)(Cb + (size_t)row * ldc + cc) = pkh2(v0, v1);
                }
            }
        }
    }
}

// ---------------- fused flash attention ----------------
__global__ void __launch_bounds__(256, 1) flash_k(const __half* __restrict__ qkv,
                                                  const __half* __restrict__ vT,
                                                  __half* __restrict__ ao) {
    extern __shared__ char dyn[];
    constexpr uint32_t QBYTES = 128 * 72 * 2;
    constexpr uint32_t KST    = 128 * 72 * 2;
    constexpr uint32_t VST    = 64 * 136 * 2;
    char* sQ = dyn;
    char* sK = dyn + QBYTES;
    char* sV = dyn + QBYTES + 2 * KST;

    int tid = threadIdx.x, wid = tid >> 5, lid = tid & 31;
    int qt = blockIdx.x, bh = blockIdx.y;
    int b = bh >> 4, h = bh & 15;
    int q0 = qt * 128;
    const __half* Qg = qkv + (size_t)b * SEQ * 3 * HID + h * 64;
    const __half* Kg = qkv + (size_t)b * SEQ * 3 * HID + HID + h * 64;
    const __half* Vt = vT + (size_t)bh * 64 * SEQ;

    uint32_t uQ = s2u(sQ), uK = s2u(sK), uV = s2u(sV);

#pragma unroll
    for (int i = 0; i < 4; i++) {
        int idx = tid + i * 256;
        int row = idx >> 3, ch = idx & 7;
        cpasync16(uQ + row * 144 + ch * 16, Qg + (size_t)(q0 + row) * 3 * HID + ch * 8);
    }
    auto loadKV = [&](int st, int kt) {
#pragma unroll
        for (int i = 0; i < 4; i++) {
            int idx = tid + i * 256;
            int row = idx >> 3, ch = idx & 7;
            cpasync16(uK + st * KST + row * 144 + ch * 16,
                      Kg + (size_t)(kt * 128 + row) * 3 * HID + ch * 8);
        }
#pragma unroll
        for (int i = 0; i < 4; i++) {
            int idx = tid + i * 256;
            int row = idx >> 4, ch = idx & 15;
            cpasync16(uV + st * VST + row * 272 + ch * 16,
                      Vt + (size_t)row * SEQ + kt * 128 + ch * 8);
        }
    };
    loadKV(0, 0);
    CP_COMMIT();

    float oacc[8][4];
#pragma unroll
    for (int j = 0; j < 8; j++)
#pragma unroll
        for (int q = 0; q < 4; q++) oacc[j][q] = 0.f;
    float m0 = -1e30f, m1 = -1e30f, l0 = 0.f, l1 = 0.f;

    int aRowL = wid * 16 + (lid & 15);
    int aColL = (lid >> 4) * 8;
    int bRowL = ((lid >> 4) << 3) + (lid & 7);
    int bColL = ((lid >> 3) & 1) * 8;

    for (int kt = 0; kt < SEQ / 128; kt++) {
        if (kt + 1 < SEQ / 128) { loadKV((kt + 1) & 1, kt + 1); CP_COMMIT(); CP_WAIT(1); }
        else CP_WAIT(0);
        __syncthreads();
        int st = kt & 1;
        uint32_t kBase = uK + st * KST;
        uint32_t vBase = uV + st * VST;

        float sacc[16][4];
#pragma unroll
        for (int t = 0; t < 16; t++)
#pragma unroll
            for (int q = 0; q < 4; q++) sacc[t][q] = 0.f;

#pragma unroll
        for (int ks = 0; ks < 4; ks++) {
            uint32_t afr[4];
            ldsm4(afr, uQ + aRowL * 144 + (ks * 16 + aColL) * 2);
#pragma unroll
            for (int nb = 0; nb < 8; nb++) {
                uint32_t bfr[4];
                ldsm4(bfr, kBase + (nb * 16 + bRowL) * 144 + (ks * 16 + bColL) * 2);
                mma16816(sacc[2 * nb],     afr, &bfr[0]);
                mma16816(sacc[2 * nb + 1], afr, &bfr[2]);
            }
        }

        float tm0 = -1e30f, tm1 = -1e30f;
#pragma unroll
        for (int t = 0; t < 16; t++) {
            sacc[t][0] *= 0.125f; sacc[t][1] *= 0.125f;
            sacc[t][2] *= 0.125f; sacc[t][3] *= 0.125f;
            tm0 = fmaxf(tm0, fmaxf(sacc[t][0], sacc[t][1]));
            tm1 = fmaxf(tm1, fmaxf(sacc[t][2], sacc[t][3]));
        }
        tm0 = fmaxf(tm0, __shfl_xor_sync(0xffffffffu, tm0, 1));
        tm0 = fmaxf(tm0, __shfl_xor_sync(0xffffffffu, tm0, 2));
        tm1 = fmaxf(tm1, __shfl_xor_sync(0xffffffffu, tm1, 1));
        tm1 = fmaxf(tm1, __shfl_xor_sync(0xffffffffu, tm1, 2));
        float nm0 = fmaxf(m0, tm0), nm1 = fmaxf(m1, tm1);
        float f0 = __expf(m0 - nm0), f1 = __expf(m1 - nm1);
        m0 = nm0; m1 = nm1;
        float rs0 = 0.f, rs1 = 0.f;
#pragma unroll
        for (int t = 0; t < 16; t++) {
            sacc[t][0] = __expf(sacc[t][0] - nm0);
            sacc[t][1] = __expf(sacc[t][1] - nm0);
            sacc[t][2] = __expf(sacc[t][2] - nm1);
            sacc[t][3] = __expf(sacc[t][3] - nm1);
            rs0 += sacc[t][0] + sacc[t][1];
            rs1 += sacc[t][2] + sacc[t][3];
        }
        rs0 += __shfl_xor_sync(0xffffffffu, rs0, 1);
        rs0 += __shfl_xor_sync(0xffffffffu, rs0, 2);
        rs1 += __shfl_xor_sync(0xffffffffu, rs1, 1);
        rs1 += __shfl_xor_sync(0xffffffffu, rs1, 2);
        l0 = l0 * f0 + rs0;
        l1 = l1 * f1 + rs1;
#pragma unroll
        for (int j = 0; j < 8; j++) {
            oacc[j][0] *= f0; oacc[j][1] *= f0;
            oacc[j][2] *= f1; oacc[j][3] *= f1;
        }

#pragma unroll
        for (int ks = 0; ks < 8; ks++) {
            uint32_t pa[4];
            pa[0] = pkh2(sacc[2 * ks][0],     sacc[2 * ks][1]);
            pa[1] = pkh2(sacc[2 * ks][2],     sacc[2 * ks][3]);
            pa[2] = pkh2(sacc[2 * ks + 1][0], sacc[2 * ks + 1][1]);
            pa[3] = pkh2(sacc[2 * ks + 1][2], sacc[2 * ks + 1][3]);
#pragma unroll
            for (int nb = 0; nb < 4; nb++) {
                uint32_t bfr[4];
                ldsm4(bfr, vBase + (nb * 16 + bRowL) * 272 + (ks * 16 + bColL) * 2);
                mma16816(oacc[2 * nb],     pa, &bfr[0]);
                mma16816(oacc[2 * nb + 1], pa, &bfr[2]);
            }
        }
        __syncthreads();
    }

    float i0 = 1.0f / l0, i1 = 1.0f / l1;
    int row = q0 + wid * 16 + (lid >> 2);
    __half* d0 = ao + ((size_t)b * SEQ + row) * HID + h * 64;
    __half* d1 = ao + ((size_t)b * SEQ + row + 8) * HID + h * 64;
#pragma unroll
    for (int j = 0; j < 8; j++) {
        int cc = j * 8 + (lid & 3) * 2;
        *(uint32_t*)(d0 + cc) = pkh2(oacc[j][0] * i0, oacc[j][1] * i0);
        *(uint32_t*)(d1 + cc) = pkh2(oacc[j][2] * i1, oacc[j][3] * i1);
    }
}

// ---------------- support kernels ----------------
__global__ void __launch_bounds__(256) f2h_k(const float* __restrict__ in, __half* __restrict__ outp, int n4) {
    int i = blockIdx.x * 256 + threadIdx.x;
    if (i >= n4) return;
    float4 v = ((const float4*)in)[i];
    ((uint2*)outp)[i] = make_uint2(pkh2(v.x, v.y), pkh2(v.z, v.w));
}

__global__ void tconv_k(const float* __restrict__ in, __half* __restrict__ outp, int R, int C) {
    __shared__ float t[32][33];
    in += (size_t)blockIdx.z * R * C;
    outp += (size_t)blockIdx.z * R * C;
    int x = blockIdx.x * 32 + threadIdx.x;
    int y0 = blockIdx.y * 32;
#pragma unroll
    for (int j = 0; j < 32; j += 8)
        t[threadIdx.y + j][threadIdx.x] = in[(size_t)(y0 + threadIdx.y + j) * C + x];
    __syncthreads();
    int ox = y0 + threadIdx.x;
    int oy0 = blockIdx.x * 32;
#pragma unroll
    for (int j = 0; j < 32; j += 8)
        outp[(size_t)(oy0 + threadIdx.y + j) * R + ox] = __float2half_rn(t[threadIdx.x][threadIdx.y + j]);
}

template <bool BOTH>
__global__ void __launch_bounds__(256) ln_k(const float* __restrict__ x, const float* __restrict__ g,
                                            const float* __restrict__ bta,
                                            __half* __restrict__ ob, float* __restrict__ of) {
    __shared__ float red[16], fin[2];
    int tid = threadIdx.x;
    size_t row = blockIdx.x;
    float4 v = ((const float4*)(x + row * HID))[tid];
    float s = v.x + v.y + v.z + v.w;
    float q = v.x * v.x + v.y * v.y + v.z * v.z + v.w * v.w;
#pragma unroll
    for (int o = 16; o; o >>= 1) {
        s += __shfl_xor_sync(0xffffffffu, s, o);
        q += __shfl_xor_sync(0xffffffffu, q, o);
    }
    if ((tid & 31) == 0) { red[tid >> 5] = s; red[8 + (tid >> 5)] = q; }
    __syncthreads();
    if (tid < 8) {
        s = red[tid]; q = red[8 + tid];
#pragma unroll
        for (int o = 4; o; o >>= 1) {
            s += __shfl_xor_sync(0xffu, s, o);
            q += __shfl_xor_sync(0xffu, q, o);
        }
        if (tid == 0) {
            float mu = s * (1.0f / HID);
            fin[0] = mu;
            fin[1] = rsqrtf(q * (1.0f / HID) - mu * mu + 1e-5f);
        }
    }
    __syncthreads();
    float mu = fin[0], rstd = fin[1];
    float4 gv = ((const float4*)g)[tid];
    float4 bv = ((const float4*)bta)[tid];
    float4 o;
    o.x = (v.x - mu) * rstd * gv.x + bv.x;
    o.y = (v.y - mu) * rstd * gv.y + bv.y;
    o.z = (v.z - mu) * rstd * gv.z + bv.z;
    o.w = (v.w - mu) * rstd * gv.w + bv.w;
    ((uint2*)(ob + row * HID))[tid] = make_uint2(pkh2(o.x, o.y), pkh2(o.z, o.w));
    if (BOTH) ((float4*)(of + row * HID))[tid] = o;
}

__global__ void __launch_bounds__(256) gate_k(const float* __restrict__ Wg) {
    int warp = (blockIdx.x * 256 + threadIdx.x) >> 5;
    int lane = threadIdx.x & 31;
    if (warp >= TOK) return;
    const float* xr = g_h2f + (size_t)warp * HID;
    float acc[8] = {0, 0, 0, 0, 0, 0, 0, 0};
    for (int hh = lane; hh < HID; hh += 32) {
        float xv = xr[hh];
        float4 w0 = *(const float4*)(Wg + hh * 8);
        float4 w1 = *(const float4*)(Wg + hh * 8 + 4);
        acc[0] += xv * w0.x; acc[1] += xv * w0.y; acc[2] += xv * w0.z; acc[3] += xv * w0.w;
        acc[4] += xv * w1.x; acc[5] += xv * w1.y; acc[6] += xv * w1.z; acc[7] += xv * w1.w;
    }
#pragma unroll
    for (int o = 16; o; o >>= 1)
#pragma unroll
        for (int e = 0; e < 8; e++) acc[e] += __shfl_xor_sync(0xffffffffu, acc[e], o);
    if (lane == 0) {
        int i0 = 0; float v0 = acc[0];
#pragma unroll
        for (int e = 1; e < 8; e++) if (acc[e] > v0) { v0 = acc[e]; i0 = e; }
        int i1 = -1; float v1 = -3.4e38f;
#pragma unroll
        for (int e = 0; e < 8; e++) if (e != i0 && acc[e] > v1) { v1 = acc[e]; i1 = e; }
        float w0 = 1.0f / (1.0f + __expf(v1 - v0));
        g_topi[2 * warp] = i0; g_topi[2 * warp + 1] = i1;
        g_topw[2 * warp] = w0; g_topw[2 * warp + 1] = 1.0f - w0;
        atomicAdd(&g_cnt[i0], 1);
        atomicAdd(&g_cnt[i1], 1);
    }
}

// merged scan + scatter (single block)
__global__ void __launch_bounds__(1024) route_k() {
    if (threadIdx.x == 0) {
        g_offs[0] = 0;
        for (int e = 0; e < NEXP; e++) g_offs[e + 1] = g_offs[e] + g_cnt[e];
    }
    __syncthreads();
    for (int idx = threadIdx.x; idx < TOK * 2; idx += 1024) {
        int e = g_topi[idx];
        int pos = atomicAdd(&g_cur[e], 1);
        int slot = g_offs[e] + pos;
        g_slottok[slot] = idx >> 1;
        g_slotof[idx] = slot;
    }
}

__global__ void __launch_bounds__(256) combine_k(float* __restrict__ outp) {
    int t = blockIdx.x;
    int j = threadIdx.x;
    float w0 = g_topw[2 * t], w1 = g_topw[2 * t + 1];
    size_t s0 = g_slotof[2 * t], s1 = g_slotof[2 * t + 1];
    float4 r  = ((const float4*)(g_xattn + (size_t)t * HID))[j];
    float4 y0 = ((const float4*)(g_Y2 + s0 * HID))[j];
    float4 y1 = ((const float4*)(g_Y2 + s1 * HID))[j];
    r.x += w0 * y0.x + w1 * y1.x;
    r.y += w0 * y0.y + w1 * y1.y;
    r.z += w0 * y0.z + w1 * y1.z;
    r.w += w0 * y0.w + w1 * y1.w;
    ((float4*)(outp + (size_t)t * HID))[j] = r;
}

#define SYM(p, s) void* p; cudaGetSymbolAddress(&p, s)

extern "C" void kernel_launch(void* const* d_in, const int* in_sizes, int n_in,
                              void* d_out, int out_size) {
    const float* x     = (const float*)d_in[0];
    const float* ln1_g = (const float*)d_in[1];
    const float* ln1_b = (const float*)d_in[2];
    const float* qkv_w = (const float*)d_in[3];
    const float* qkv_b = (const float*)d_in[4];
    const float* out_w = (const float*)d_in[5];
    const float* out_b = (const float*)d_in[6];
    const float* ln2_g = (const float*)d_in[7];
    const float* ln2_b = (const float*)d_in[8];
    const float* Wg    = (const float*)d_in[9];
    const float* W1    = (const float*)d_in[10];
    const float* b1    = (const float*)d_in[11];
    const float* W2    = (const float*)d_in[12];
    const float* b2    = (const float*)d_in[13];
    float* outp = (float*)d_out;

    SYM(p_hln, gb_hln);   SYM(p_qkvw, gb_qkvw); SYM(p_outw, gb_outw);
    SYM(p_w1t, gb_w1t);   SYM(p_w2t, gb_w2t);   SYM(p_qkv, gb_qkv);
    SYM(p_vT, gb_vT);     SYM(p_ao, gb_ao);     SYM(p_h2b, gb_h2);
    SYM(p_H1, gb_H1);     SYM(p_xattn, g_xattn); SYM(p_h2f, g_h2f);
    SYM(p_Y2, g_Y2);      SYM(p_cnt, g_cnt);    SYM(p_cur, g_cur);
    SYM(p_slottok, g_slottok); SYM(p_offs, g_offs);

    constexpr int GEMM_SMEM = STAGES3 * (128 + 128) * 144;  // 110592
    cudaFuncSetAttribute(hgemm<0, 128>, cudaFuncAttributeMaxDynamicSharedMemorySize, GEMM_SMEM);
    cudaFuncSetAttribute(hgemm<1, 128>, cudaFuncAttributeMaxDynamicSharedMemorySize, GEMM_SMEM);
    cudaFuncSetAttribute(hgemm<4, 128>, cudaFuncAttributeMaxDynamicSharedMemorySize, GEMM_SMEM);
    cudaFuncSetAttribute(hgemm<5, 128>, cudaFuncAttributeMaxDynamicSharedMemorySize, GEMM_SMEM);
    constexpr int FLASH_SMEM = (128 * 72 * 2) * 3 + (64 * 136 * 2) * 2;  // 90112
    cudaFuncSetAttribute(flash_k, cudaFuncAttributeMaxDynamicSharedMemorySize, FLASH_SMEM);

    cudaStream_t s2;
    cudaStreamCreateWithFlags(&s2, cudaStreamNonBlocking);
    cudaEvent_t evFork, evJoin;
    cudaEventCreateWithFlags(&evFork, cudaEventDisableTiming);
    cudaEventCreateWithFlags(&evJoin, cudaEventDisableTiming);

    cudaEventRecord(evFork, 0);
    cudaStreamWaitEvent(s2, evFork, 0);

    dim3 tb(32, 8);
    // side stream: MoE weight transposes, out_w convert, routing counters
    tconv_k<<<dim3(FDIM / 32, HID / 32, NEXP), tb, 0, s2>>>(W1, (__half*)p_w1t, HID, FDIM);
    tconv_k<<<dim3(HID / 32, FDIM / 32, NEXP), tb, 0, s2>>>(W2, (__half*)p_w2t, FDIM, HID);
    f2h_k<<<(HID * HID / 4 + 255) / 256, 256, 0, s2>>>(out_w, (__half*)p_outw, HID * HID / 4);
    cudaMemsetAsync(p_cnt, 0, NEXP * sizeof(int), s2);
    cudaMemsetAsync(p_cur, 0, NEXP * sizeof(int), s2);
    cudaEventRecord(evJoin, s2);

    // main stream: attention phase
    f2h_k<<<(3 * HID * HID / 4 + 255) / 256, 256>>>(qkv_w, (__half*)p_qkvw, 3 * HID * HID / 4);
    ln_k<false><<<TOK, 256>>>(x, ln1_g, ln1_b, (__half*)p_hln, nullptr);

    // QKV GEMM: q/k -> gb_qkv, v -> gb_vT (fused transpose in epilogue)
    hgemm<0, 128><<<dim3(3 * HID / 128, TOK / 128, 1), 256, GEMM_SMEM>>>(
        (const __half*)p_hln, (const __half*)p_qkvw, p_qkv,
        TOK, 3 * HID, HID, HID, HID, 3 * HID, qkv_b, nullptr, nullptr, nullptr);

    flash_k<<<dim3(SEQ / 128, 2 * NHEAD), 256, FLASH_SMEM>>>(
        (const __half*)p_qkv, (const __half*)p_vT, (__half*)p_ao);

    cudaStreamWaitEvent(0, evJoin, 0);

    hgemm<1, 128><<<dim3(HID / 128, TOK / 128, 1), 256, GEMM_SMEM>>>(
        (const __half*)p_ao, (const __half*)p_outw, p_xattn,
        TOK, HID, HID, HID, HID, HID, out_b, x, nullptr, nullptr);

    ln_k<true><<<TOK, 256>>>((const float*)p_xattn, ln2_g, ln2_b,
                             (__half*)p_h2b, (float*)p_h2f);

    gate_k<<<TOK / 8, 256>>>(Wg);
    route_k<<<1, 1024>>>();

    hgemm<4, 128><<<dim3(FDIM / 128, NSLOT / 128, NEXP), 256, GEMM_SMEM>>>(
        (const __half*)p_h2b, (const __half*)p_w1t, p_H1,
        0, FDIM, HID, HID, HID, FDIM, b1, nullptr, (const int*)p_slottok, (const int*)p_offs);

    hgemm<5, 128><<<dim3(HID / 128, NSLOT / 128, NEXP), 256, GEMM_SMEM>>>(
        (const __half*)p_H1, (const __half*)p_w2t, p_Y2,
        0, HID, FDIM, FDIM, FDIM, HID, b2, nullptr, nullptr, (const int*)p_offs);

    combine_k<<<TOK, 256>>>(outp);

    cudaStreamDestroy(s2);
    cudaEventDestroy(evFork);
    cudaEventDestroy(evJoin);
}

// round 15
// speedup vs baseline: 1.0698x; 1.0130x over previous
#include <cuda_runtime.h>
#include <cuda_fp16.h>
#include <cstdint>
#include <cstddef>

#define TOK   4096
#define SEQ   2048
#define HID   1024
#define NHEAD 16
#define NEXP  8
#define FDIM  4096
#define NSLOT 8192

// ---------------- scratch ----------------
__device__ __align__(128) __half gb_hln [(size_t)TOK * HID];
__device__ __align__(128) __half gb_qkvw[(size_t)3 * HID * HID];
__device__ __align__(128) __half gb_outw[(size_t)HID * HID];
__device__ __align__(128) __half gb_w1t [(size_t)NEXP * FDIM * HID];
__device__ __align__(128) __half gb_w2t [(size_t)NEXP * HID * FDIM];
__device__ __align__(128) __half gb_qkv [(size_t)TOK * 3 * HID];
__device__ __align__(128) __half gb_vT  [(size_t)2 * NHEAD * 64 * SEQ];
__device__ __align__(128) __half gb_ao  [(size_t)TOK * HID];
__device__ __align__(128) __half gb_h2  [(size_t)TOK * HID];
__device__ __align__(128) __half gb_H1  [(size_t)NSLOT * FDIM];
__device__ float g_xattn[(size_t)TOK * HID];
__device__ float g_h2f  [(size_t)TOK * HID];
__device__ float g_Y2   [(size_t)NSLOT * HID];
__device__ int   g_topi [TOK * 2];
__device__ float g_topw [TOK * 2];
__device__ int   g_cnt  [NEXP];
__device__ int   g_offs [NEXP + 1];
__device__ int   g_cur  [NEXP];
__device__ int   g_slottok[NSLOT];
__device__ int   g_slotof [TOK * 2];

// ---------------- PTX helpers ----------------
__device__ __forceinline__ uint32_t s2u(const void* p) {
    uint32_t a;
    asm("{ .reg .u64 t; cvta.to.shared.u64 t, %1; cvt.u32.u64 %0, t; }" : "=r"(a) : "l"(p));
    return a;
}
__device__ __forceinline__ void cpasync16(uint32_t saddr, const void* g) {
    asm volatile("cp.async.cg.shared.global [%0], [%1], 16;" :: "r"(saddr), "l"(g));
}
#define CP_COMMIT() asm volatile("cp.async.commit_group;" ::: "memory")
#define CP_WAIT(n)  asm volatile("cp.async.wait_group %0;" :: "n"(n) : "memory")

__device__ __forceinline__ void ldsm4(uint32_t* r, uint32_t addr) {
    asm volatile("ldmatrix.sync.aligned.m8n8.x4.shared.b16 {%0,%1,%2,%3}, [%4];"
                 : "=r"(r[0]), "=r"(r[1]), "=r"(r[2]), "=r"(r[3]) : "r"(addr));
}
__device__ __forceinline__ void mma16816(float* c, const uint32_t* a, const uint32_t* b) {
    asm volatile("mma.sync.aligned.m16n8k16.row.col.f32.f16.f16.f32 "
                 "{%0,%1,%2,%3}, {%4,%5,%6,%7}, {%8,%9}, {%0,%1,%2,%3};"
                 : "+f"(c[0]), "+f"(c[1]), "+f"(c[2]), "+f"(c[3])
                 : "r"(a[0]), "r"(a[1]), "r"(a[2]), "r"(a[3]), "r"(b[0]), "r"(b[1]));
}
__device__ __forceinline__ float gelu_tanh(float x) {
    float u = 0.7978845608028654f * (x + 0.044715f * x * x * x);
    u = fminf(fmaxf(u, -15.0f), 15.0f);
    float e = __expf(2.0f * u);
    return x * e / (e + 1.0f);
}
__device__ __forceinline__ uint32_t pkh2(float a, float b) {
    __half2 t = __floats2half2_rn(a, b);
    return *(uint32_t*)&t;
}

// ---------------- HMMA GEMM: BK=64 chunks, 3-stage cp.async ring ----------------
// pitch 72 halves (144B) per row — conflict-free for ldsm.
// Invariant: one commit per iteration (empty past tail); CP_WAIT(1) at iter c
// proves chunk c resident; stage (c+2)%3 was last read at iter c-1, protected
// by iter-c's barrier.
// MODE 0: QKV (+bias; q/k -> gb_qkv, v -> gb_vT transposed)
// MODE 1: outproj (+bias+res, f32 out)
// MODE 4: MoE1 (gather rows, +b1, gelu, f16 out)   MODE 5: MoE2 (+b2, f32 out)
#define STAGES3 3
template <int MODE, int NT>
__global__ void __launch_bounds__(256, 2) hgemm(
    const __half* __restrict__ A, const __half* __restrict__ B, void* Cv,
    int M, int N, int K, int lda, int ldb, int ldc,
    const float* __restrict__ bias, const float* __restrict__ res,
    const int* __restrict__ gtok, const int* __restrict__ offs) {
    extern __shared__ __align__(128) char dsm[];
    constexpr uint32_t AST = 128 * 144;     // 128 rows x 72 halves
    constexpr uint32_t BST = NT * 144;

    int tid = threadIdx.x, wid = tid >> 5, lid = tid & 31;
    int z = blockIdx.z;
    const __half* Ab = A;
    const __half* Bb = B;
    float* Cf = (float*)Cv;
    __half* Cb = (__half*)Cv;
    const float* biasb = bias;
    int r0 = 0, r1 = M;
    if (MODE == 4 || MODE == 5) {
        r0 = offs[z]; r1 = offs[z + 1];
        Bb = B + (size_t)z * (size_t)N * K;
        biasb = bias + (size_t)z * N;
    }
    int rowBase = r0 + blockIdx.y * 128;
    if (rowBase >= r1) return;
    int n0 = blockIdx.x * NT;

    constexpr int WN = NT / 4;
    constexpr int NTILES = WN / 8;
    int wm = (wid >> 2) * 64;
    int wn = (wid & 3) * WN;

    uint32_t uAs = s2u(dsm);
    uint32_t uBs = uAs + STAGES3 * AST;

    int aRowL = wm + (lid & 15);
    int aColL = (lid >> 4) * 8;
    int bRowL = wn + ((lid >> 4) << 3) + (lid & 7);
    int bColL = ((lid >> 3) & 1) * 8;

    float acc[4][NTILES][4];
#pragma unroll
    for (int i = 0; i < 4; i++)
#pragma unroll
        for (int j = 0; j < NTILES; j++)
#pragma unroll
            for (int q = 0; q < 4; q++) acc[i][j][q] = 0.f;

    int ldRow = tid >> 3, ldCh = tid & 7;
    const __half* aSrc[4];
#pragma unroll
    for (int i = 0; i < 4; i++) {
        int gr = rowBase + ldRow + i * 32;
        if (gr > r1 - 1) gr = r1 - 1;
        aSrc[i] = Ab + (size_t)((MODE == 4) ? gtok[gr] : gr) * lda;
    }

    auto loadStage = [&](int st, int c) {
        int kt = c * 64;
#pragma unroll
        for (int i = 0; i < 4; i++)
            cpasync16(uAs + st * AST + (ldRow + i * 32) * 144 + ldCh * 16,
                      aSrc[i] + kt + ldCh * 8);
#pragma unroll
        for (int i = 0; i < NT / 32; i++) {
            int row = ldRow + i * 32;
            cpasync16(uBs + st * BST + row * 144 + ldCh * 16,
                      Bb + (size_t)(n0 + row) * ldb + kt + ldCh * 8);
        }
    };

    int nk = K / 64;
    loadStage(0, 0); CP_COMMIT();
    loadStage(1, 1); CP_COMMIT();

    int cSt = 0, ldSt = 2;
    for (int c = 0; c < nk; c++) {
        CP_WAIT(1);
        __syncthreads();
        if (c + 2 < nk) loadStage(ldSt, c + 2);
        CP_COMMIT();   // always commit — keeps the wait invariant at the tail
        uint32_t aBase = uAs + cSt * AST;
        uint32_t bBase = uBs + cSt * BST;
#pragma unroll
        for (int ks = 0; ks < 4; ks++) {
            uint32_t afr[4][4];
#pragma unroll
            for (int mt = 0; mt < 4; mt++)
                ldsm4(afr[mt], aBase + (aRowL + mt * 16) * 144 + (ks * 16 + aColL) * 2);
#pragma unroll
            for (int nb = 0; nb < NTILES / 2; nb++) {
                uint32_t bfr[4];
                ldsm4(bfr, bBase + (bRowL + nb * 16) * 144 + (ks * 16 + bColL) * 2);
#pragma unroll
                for (int mt = 0; mt < 4; mt++) {
                    mma16816(acc[mt][2 * nb],     afr[mt], &bfr[0]);
                    mma16816(acc[mt][2 * nb + 1], afr[mt], &bfr[2]);
                }
            }
        }
        cSt  = (cSt  == 2) ? 0 : cSt + 1;
        ldSt = (ldSt == 2) ? 0 : ldSt + 1;
    }

#pragma unroll
    for (int mt = 0; mt < 4; mt++) {
#pragma unroll
        for (int h = 0; h < 2; h++) {
            int row = rowBase + wm + mt * 16 + h * 8 + (lid >> 2);
            if (row >= r1) continue;
#pragma unroll
            for (int nt = 0; nt < NTILES; nt++) {
                float v0 = acc[mt][nt][2 * h], v1 = acc[mt][nt][2 * h + 1];
                int cc = n0 + wn + nt * 8 + 2 * (lid & 3);
                if (MODE == 0) { v0 += bias[cc]; v1 += bias[cc + 1]; }
                if (MODE == 1) {
                    float2 rr = *(const float2*)(res + (size_t)row * ldc + cc);
                    v0 += bias[cc] + rr.x; v1 += bias[cc + 1] + rr.y;
                }
                if (MODE == 4) {
                    v0 = gelu_tanh(v0 + biasb[cc]);
                    v1 = gelu_tanh(v1 + biasb[cc + 1]);
                }
                if (MODE == 5) { v0 += biasb[cc]; v1 += biasb[cc + 1]; }
                if (MODE == 1 || MODE == 5) {
                    *(float2*)(Cf + (size_t)row * ldc + cc) = make_float2(v0, v1);
                } else if (MODE == 0 && cc >= 2 * HID) {
                    // V-section: write straight into per-head V^T (fused vtrans)
                    int d = cc - 2 * HID;
                    int hh = d >> 6, dd = d & 63;
                    int bb = row >> 11, ss = row & 2047;
                    uint32_t pk = pkh2(v0, v1);
                    __half2 pr = *(__half2*)&pk;
                    __half* vb = gb_vT + ((size_t)(bb * NHEAD + hh) * 64 + dd) * SEQ + ss;
                    vb[0]   = __low2half(pr);
                    vb[SEQ] = __high2half(pr);
                } else {
                    *(uint32_t*)(Cb + (size_t)row * ldc + cc) = pkh2(v0, v1);
                }
            }
        }
    }
}

// ---------------- fused flash attention (occ 2 experiment) ----------------
__global__ void __launch_bounds__(256, 2) flash_k(const __half* __restrict__ qkv,
                                                  const __half* __restrict__ vT,
                                                  __half* __restrict__ ao) {
    extern __shared__ char dyn[];
    constexpr uint32_t QBYTES = 128 * 72 * 2;
    constexpr uint32_t KST    = 128 * 72 * 2;
    constexpr uint32_t VST    = 64 * 136 * 2;
    char* sQ = dyn;
    char* sK = dyn + QBYTES;
    char* sV = dyn + QBYTES + 2 * KST;

    int tid = threadIdx.x, wid = tid >> 5, lid = tid & 31;
    int qt = blockIdx.x, bh = blockIdx.y;
    int b = bh >> 4, h = bh & 15;
    int q0 = qt * 128;
    const __half* Qg = qkv + (size_t)b * SEQ * 3 * HID + h * 64;
    const __half* Kg = qkv + (size_t)b * SEQ * 3 * HID + HID + h * 64;
    const __half* Vt = vT + (size_t)bh * 64 * SEQ;

    uint32_t uQ = s2u(sQ), uK = s2u(sK), uV = s2u(sV);

#pragma unroll
    for (int i = 0; i < 4; i++) {
        int idx = tid + i * 256;
        int row = idx >> 3, ch = idx & 7;
        cpasync16(uQ + row * 144 + ch * 16, Qg + (size_t)(q0 + row) * 3 * HID + ch * 8);
    }
    auto loadKV = [&](int st, int kt) {
#pragma unroll
        for (int i = 0; i < 4; i++) {
            int idx = tid + i * 256;
            int row = idx >> 3, ch = idx & 7;
            cpasync16(uK + st * KST + row * 144 + ch * 16,
                      Kg + (size_t)(kt * 128 + row) * 3 * HID + ch * 8);
        }
#pragma unroll
        for (int i = 0; i < 4; i++) {
            int idx = tid + i * 256;
            int row = idx >> 4, ch = idx & 15;
            cpasync16(uV + st * VST + row * 272 + ch * 16,
                      Vt + (size_t)row * SEQ + kt * 128 + ch * 8);
        }
    };
    loadKV(0, 0);
    CP_COMMIT();

    float oacc[8][4];
#pragma unroll
    for (int j = 0; j < 8; j++)
#pragma unroll
        for (int q = 0; q < 4; q++) oacc[j][q] = 0.f;
    float m0 = -1e30f, m1 = -1e30f, l0 = 0.f, l1 = 0.f;

    int aRowL = wid * 16 + (lid & 15);
    int aColL = (lid >> 4) * 8;
    int bRowL = ((lid >> 4) << 3) + (lid & 7);
    int bColL = ((lid >> 3) & 1) * 8;

    for (int kt = 0; kt < SEQ / 128; kt++) {
        if (kt + 1 < SEQ / 128) { loadKV((kt + 1) & 1, kt + 1); CP_COMMIT(); CP_WAIT(1); }
        else CP_WAIT(0);
        __syncthreads();
        int st = kt & 1;
        uint32_t kBase = uK + st * KST;
        uint32_t vBase = uV + st * VST;

        float sacc[16][4];
#pragma unroll
        for (int t = 0; t < 16; t++)
#pragma unroll
            for (int q = 0; q < 4; q++) sacc[t][q] = 0.f;

#pragma unroll
        for (int ks = 0; ks < 4; ks++) {
            uint32_t afr[4];
            ldsm4(afr, uQ + aRowL * 144 + (ks * 16 + aColL) * 2);
#pragma unroll
            for (int nb = 0; nb < 8; nb++) {
                uint32_t bfr[4];
                ldsm4(bfr, kBase + (nb * 16 + bRowL) * 144 + (ks * 16 + bColL) * 2);
                mma16816(sacc[2 * nb],     afr, &bfr[0]);
                mma16816(sacc[2 * nb + 1], afr, &bfr[2]);
            }
        }

        float tm0 = -1e30f, tm1 = -1e30f;
#pragma unroll
        for (int t = 0; t < 16; t++) {
            sacc[t][0] *= 0.125f; sacc[t][1] *= 0.125f;
            sacc[t][2] *= 0.125f; sacc[t][3] *= 0.125f;
            tm0 = fmaxf(tm0, fmaxf(sacc[t][0], sacc[t][1]));
            tm1 = fmaxf(tm1, fmaxf(sacc[t][2], sacc[t][3]));
        }
        tm0 = fmaxf(tm0, __shfl_xor_sync(0xffffffffu, tm0, 1));
        tm0 = fmaxf(tm0, __shfl_xor_sync(0xffffffffu, tm0, 2));
        tm1 = fmaxf(tm1, __shfl_xor_sync(0xffffffffu, tm1, 1));
        tm1 = fmaxf(tm1, __shfl_xor_sync(0xffffffffu, tm1, 2));
        float nm0 = fmaxf(m0, tm0), nm1 = fmaxf(m1, tm1);
        float f0 = __expf(m0 - nm0), f1 = __expf(m1 - nm1);
        m0 = nm0; m1 = nm1;
        float rs0 = 0.f, rs1 = 0.f;
#pragma unroll
        for (int t = 0; t < 16; t++) {
            sacc[t][0] = __expf(sacc[t][0] - nm0);
            sacc[t][1] = __expf(sacc[t][1] - nm0);
            sacc[t][2] = __expf(sacc[t][2] - nm1);
            sacc[t][3] = __expf(sacc[t][3] - nm1);
            rs0 += sacc[t][0] + sacc[t][1];
            rs1 += sacc[t][2] + sacc[t][3];
        }
        rs0 += __shfl_xor_sync(0xffffffffu, rs0, 1);
        rs0 += __shfl_xor_sync(0xffffffffu, rs0, 2);
        rs1 += __shfl_xor_sync(0xffffffffu, rs1, 1);
        rs1 += __shfl_xor_sync(0xffffffffu, rs1, 2);
        l0 = l0 * f0 + rs0;
        l1 = l1 * f1 + rs1;
#pragma unroll
        for (int j = 0; j < 8; j++) {
            oacc[j][0] *= f0; oacc[j][1] *= f0;
            oacc[j][2] *= f1; oacc[j][3] *= f1;
        }

#pragma unroll
        for (int ks = 0; ks < 8; ks++) {
            uint32_t pa[4];
            pa[0] = pkh2(sacc[2 * ks][0],     sacc[2 * ks][1]);
            pa[1] = pkh2(sacc[2 * ks][2],     sacc[2 * ks][3]);
            pa[2] = pkh2(sacc[2 * ks + 1][0], sacc[2 * ks + 1][1]);
            pa[3] = pkh2(sacc[2 * ks + 1][2], sacc[2 * ks + 1][3]);
#pragma unroll
            for (int nb = 0; nb < 4; nb++) {
                uint32_t bfr[4];
                ldsm4(bfr, vBase + (nb * 16 + bRowL) * 272 + (ks * 16 + bColL) * 2);
                mma16816(oacc[2 * nb],     pa, &bfr[0]);
                mma16816(oacc[2 * nb + 1], pa, &bfr[2]);
            }
        }
        __syncthreads();
    }

    float i0 = 1.0f / l0, i1 = 1.0f / l1;
    int row = q0 + wid * 16 + (lid >> 2);
    __half* d0 = ao + ((size_t)b * SEQ + row) * HID + h * 64;
    __half* d1 = ao + ((size_t)b * SEQ + row + 8) * HID + h * 64;
#pragma unroll
    for (int j = 0; j < 8; j++) {
        int cc = j * 8 + (lid & 3) * 2;
        *(uint32_t*)(d0 + cc) = pkh2(oacc[j][0] * i0, oacc[j][1] * i0);
        *(uint32_t*)(d1 + cc) = pkh2(oacc[j][2] * i1, oacc[j][3] * i1);
    }
}

// ---------------- support kernels ----------------
__global__ void __launch_bounds__(256) f2h_k(const float* __restrict__ in, __half* __restrict__ outp, int n4) {
    int i = blockIdx.x * 256 + threadIdx.x;
    if (i >= n4) return;
    float4 v = ((const float4*)in)[i];
    ((uint2*)outp)[i] = make_uint2(pkh2(v.x, v.y), pkh2(v.z, v.w));
}

__global__ void tconv_k(const float* __restrict__ in, __half* __restrict__ outp, int R, int C) {
    __shared__ float t[32][33];
    in += (size_t)blockIdx.z * R * C;
    outp += (size_t)blockIdx.z * R * C;
    int x = blockIdx.x * 32 + threadIdx.x;
    int y0 = blockIdx.y * 32;
#pragma unroll
    for (int j = 0; j < 32; j += 8)
        t[threadIdx.y + j][threadIdx.x] = in[(size_t)(y0 + threadIdx.y + j) * C + x];
    __syncthreads();
    int ox = y0 + threadIdx.x;
    int oy0 = blockIdx.x * 32;
#pragma unroll
    for (int j = 0; j < 32; j += 8)
        outp[(size_t)(oy0 + threadIdx.y + j) * R + ox] = __float2half_rn(t[threadIdx.x][threadIdx.y + j]);
}

template <bool BOTH>
__global__ void __launch_bounds__(256) ln_k(const float* __restrict__ x, const float* __restrict__ g,
                                            const float* __restrict__ bta,
                                            __half* __restrict__ ob, float* __restrict__ of) {
    __shared__ float red[16], fin[2];
    int tid = threadIdx.x;
    size_t row = blockIdx.x;
    float4 v = ((const float4*)(x + row * HID))[tid];
    float s = v.x + v.y + v.z + v.w;
    float q = v.x * v.x + v.y * v.y + v.z * v.z + v.w * v.w;
#pragma unroll
    for (int o = 16; o; o >>= 1) {
        s += __shfl_xor_sync(0xffffffffu, s, o);
        q += __shfl_xor_sync(0xffffffffu, q, o);
    }
    if ((tid & 31) == 0) { red[tid >> 5] = s; red[8 + (tid >> 5)] = q; }
    __syncthreads();
    if (tid < 8) {
        s = red[tid]; q = red[8 + tid];
#pragma unroll
        for (int o = 4; o; o >>= 1) {
            s += __shfl_xor_sync(0xffu, s, o);
            q += __shfl_xor_sync(0xffu, q, o);
        }
        if (tid == 0) {
            float mu = s * (1.0f / HID);
            fin[0] = mu;
            fin[1] = rsqrtf(q * (1.0f / HID) - mu * mu + 1e-5f);
        }
    }
    __syncthreads();
    float mu = fin[0], rstd = fin[1];
    float4 gv = ((const float4*)g)[tid];
    float4 bv = ((const float4*)bta)[tid];
    float4 o;
    o.x = (v.x - mu) * rstd * gv.x + bv.x;
    o.y = (v.y - mu) * rstd * gv.y + bv.y;
    o.z = (v.z - mu) * rstd * gv.z + bv.z;
    o.w = (v.w - mu) * rstd * gv.w + bv.w;
    ((uint2*)(ob + row * HID))[tid] = make_uint2(pkh2(o.x, o.y), pkh2(o.z, o.w));
    if (BOTH) ((float4*)(of + row * HID))[tid] = o;
}

__global__ void __launch_bounds__(256) gate_k(const float* __restrict__ Wg) {
    int warp = (blockIdx.x * 256 + threadIdx.x) >> 5;
    int lane = threadIdx.x & 31;
    if (warp >= TOK) return;
    const float* xr = g_h2f + (size_t)warp * HID;
    float acc[8] = {0, 0, 0, 0, 0, 0, 0, 0};
    for (int hh = lane; hh < HID; hh += 32) {
        float xv = xr[hh];
        float4 w0 = *(const float4*)(Wg + hh * 8);
        float4 w1 = *(const float4*)(Wg + hh * 8 + 4);
        acc[0] += xv * w0.x; acc[1] += xv * w0.y; acc[2] += xv * w0.z; acc[3] += xv * w0.w;
        acc[4] += xv * w1.x; acc[5] += xv * w1.y; acc[6] += xv * w1.z; acc[7] += xv * w1.w;
    }
#pragma unroll
    for (int o = 16; o; o >>= 1)
#pragma unroll
        for (int e = 0; e < 8; e++) acc[e] += __shfl_xor_sync(0xffffffffu, acc[e], o);
    if (lane == 0) {
        int i0 = 0; float v0 = acc[0];
#pragma unroll
        for (int e = 1; e < 8; e++) if (acc[e] > v0) { v0 = acc[e]; i0 = e; }
        int i1 = -1; float v1 = -3.4e38f;
#pragma unroll
        for (int e = 0; e < 8; e++) if (e != i0 && acc[e] > v1) { v1 = acc[e]; i1 = e; }
        float w0 = 1.0f / (1.0f + __expf(v1 - v0));
        g_topi[2 * warp] = i0; g_topi[2 * warp + 1] = i1;
        g_topw[2 * warp] = w0; g_topw[2 * warp + 1] = 1.0f - w0;
        atomicAdd(&g_cnt[i0], 1);
        atomicAdd(&g_cnt[i1], 1);
    }
}

__global__ void __launch_bounds__(1024) route_k() {
    if (threadIdx.x == 0) {
        g_offs[0] = 0;
        for (int e = 0; e < NEXP; e++) g_offs[e + 1] = g_offs[e] + g_cnt[e];
    }
    __syncthreads();
    for (int idx = threadIdx.x; idx < TOK * 2; idx += 1024) {
        int e = g_topi[idx];
        int pos = atomicAdd(&g_cur[e], 1);
        int slot = g_offs[e] + pos;
        g_slottok[slot] = idx >> 1;
        g_slotof[idx] = slot;
    }
}

__global__ void __launch_bounds__(256) combine_k(float* __restrict__ outp) {
    int t = blockIdx.x;
    int j = threadIdx.x;
    float w0 = g_topw[2 * t], w1 = g_topw[2 * t + 1];
    size_t s0 = g_slotof[2 * t], s1 = g_slotof[2 * t + 1];
    float4 r  = ((const float4*)(g_xattn + (size_t)t * HID))[j];
    float4 y0 = ((const float4*)(g_Y2 + s0 * HID))[j];
    float4 y1 = ((const float4*)(g_Y2 + s1 * HID))[j];
    r.x += w0 * y0.x + w1 * y1.x;
    r.y += w0 * y0.y + w1 * y1.y;
    r.z += w0 * y0.z + w1 * y1.z;
    r.w += w0 * y0.w + w1 * y1.w;
    ((float4*)(outp + (size_t)t * HID))[j] = r;
}

#define SYM(p, s) void* p; cudaGetSymbolAddress(&p, s)

extern "C" void kernel_launch(void* const* d_in, const int* in_sizes, int n_in,
                              void* d_out, int out_size) {
    const float* x     = (const float*)d_in[0];
    const float* ln1_g = (const float*)d_in[1];
    const float* ln1_b = (const float*)d_in[2];
    const float* qkv_w = (const float*)d_in[3];
    const float* qkv_b = (const float*)d_in[4];
    const float* out_w = (const float*)d_in[5];
    const float* out_b = (const float*)d_in[6];
    const float* ln2_g = (const float*)d_in[7];
    const float* ln2_b = (const float*)d_in[8];
    const float* Wg    = (const float*)d_in[9];
    const float* W1    = (const float*)d_in[10];
    const float* b1    = (const float*)d_in[11];
    const float* W2    = (const float*)d_in[12];
    const float* b2    = (const float*)d_in[13];
    float* outp = (float*)d_out;

    SYM(p_hln, gb_hln);   SYM(p_qkvw, gb_qkvw); SYM(p_outw, gb_outw);
    SYM(p_w1t, gb_w1t);   SYM(p_w2t, gb_w2t);   SYM(p_qkv, gb_qkv);
    SYM(p_vT, gb_vT);     SYM(p_ao, gb_ao);     SYM(p_h2b, gb_h2);
    SYM(p_H1, gb_H1);     SYM(p_xattn, g_xattn); SYM(p_h2f, g_h2f);
    SYM(p_Y2, g_Y2);      SYM(p_cnt, g_cnt);    SYM(p_cur, g_cur);
    SYM(p_slottok, g_slottok); SYM(p_offs, g_offs);

    constexpr int GEMM_SMEM = STAGES3 * (128 + 128) * 144;  // 110592
    cudaFuncSetAttribute(hgemm<0, 128>, cudaFuncAttributeMaxDynamicSharedMemorySize, GEMM_SMEM);
    cudaFuncSetAttribute(hgemm<1, 128>, cudaFuncAttributeMaxDynamicSharedMemorySize, GEMM_SMEM);
    cudaFuncSetAttribute(hgemm<4, 128>, cudaFuncAttributeMaxDynamicSharedMemorySize, GEMM_SMEM);
    cudaFuncSetAttribute(hgemm<5, 128>, cudaFuncAttributeMaxDynamicSharedMemorySize, GEMM_SMEM);
    constexpr int FLASH_SMEM = (128 * 72 * 2) * 3 + (64 * 136 * 2) * 2;  // 90112
    cudaFuncSetAttribute(flash_k, cudaFuncAttributeMaxDynamicSharedMemorySize, FLASH_SMEM);

    cudaStream_t s2;
    cudaStreamCreateWithFlags(&s2, cudaStreamNonBlocking);
    cudaEvent_t evFork, evJoin;
    cudaEventCreateWithFlags(&evFork, cudaEventDisableTiming);
    cudaEventCreateWithFlags(&evJoin, cudaEventDisableTiming);

    cudaEventRecord(evFork, 0);
    cudaStreamWaitEvent(s2, evFork, 0);

    dim3 tb(32, 8);
    tconv_k<<<dim3(FDIM / 32, HID / 32, NEXP), tb, 0, s2>>>(W1, (__half*)p_w1t, HID, FDIM);
    tconv_k<<<dim3(HID / 32, FDIM / 32, NEXP), tb, 0, s2>>>(W2, (__half*)p_w2t, FDIM, HID);
    f2h_k<<<(HID * HID / 4 + 255) / 256, 256, 0, s2>>>(out_w, (__half*)p_outw, HID * HID / 4);
    cudaMemsetAsync(p_cnt, 0, NEXP * sizeof(int), s2);
    cudaMemsetAsync(p_cur, 0, NEXP * sizeof(int), s2);
    cudaEventRecord(evJoin, s2);

    f2h_k<<<(3 * HID * HID / 4 + 255) / 256, 256>>>(qkv_w, (__half*)p_qkvw, 3 * HID * HID / 4);
    ln_k<false><<<TOK, 256>>>(x, ln1_g, ln1_b, (__half*)p_hln, nullptr);

    hgemm<0, 128><<<dim3(3 * HID / 128, TOK / 128, 1), 256, GEMM_SMEM>>>(
        (const __half*)p_hln, (const __half*)p_qkvw, p_qkv,
        TOK, 3 * HID, HID, HID, HID, 3 * HID, qkv_b, nullptr, nullptr, nullptr);

    flash_k<<<dim3(SEQ / 128, 2 * NHEAD), 256, FLASH_SMEM>>>(
        (const __half*)p_qkv, (const __half*)p_vT, (__half*)p_ao);

    cudaStreamWaitEvent(0, evJoin, 0);

    hgemm<1, 128><<<dim3(HID / 128, TOK / 128, 1), 256, GEMM_SMEM>>>(
        (const __half*)p_ao, (const __half*)p_outw, p_xattn,
        TOK, HID, HID, HID, HID, HID, out_b, x, nullptr, nullptr);

    ln_k<true><<<TOK, 256>>>((const float*)p_xattn, ln2_g, ln2_b,
                             (__half*)p_h2b, (float*)p_h2f);

    gate_k<<<TOK / 8, 256>>>(Wg);
    route_k<<<1, 1024>>>();

    hgemm<4, 128><<<dim3(FDIM / 128, NSLOT / 128, NEXP), 256, GEMM_SMEM>>>(
        (const __half*)p_h2b, (const __half*)p_w1t, p_H1,
        0, FDIM, HID, HID, HID, FDIM, b1, nullptr, (const int*)p_slottok, (const int*)p_offs);

    hgemm<5, 128><<<dim3(HID / 128, NSLOT / 128, NEXP), 256, GEMM_SMEM>>>(
        (const __half*)p_H1, (const __half*)p_w2t, p_Y2,
        0, HID, FDIM, FDIM, FDIM, HID, b2, nullptr, nullptr, (const int*)p_offs);

    combine_k<<<TOK, 256>>>(outp);

    cudaStreamDestroy(s2);
    cudaEventDestroy(evFork);
    cudaEventDestroy(evJoin);
}

// round 16
// speedup vs baseline: 1.0848x; 1.0140x over previous
#include <cuda_runtime.h>
#include <cuda_fp16.h>
#include <cstdint>
#include <cstddef>

#define TOK   4096
#define SEQ   2048
#define HID   1024
#define NHEAD 16
#define NEXP  8
#define FDIM  4096
#define NSLOT 8192

// ---------------- scratch ----------------
__device__ __align__(128) __half gb_hln [(size_t)TOK * HID];
__device__ __align__(128) __half gb_qkvw[(size_t)3 * HID * HID];
__device__ __align__(128) __half gb_outw[(size_t)HID * HID];
__device__ __align__(128) __half gb_w1t [(size_t)NEXP * FDIM * HID];
__device__ __align__(128) __half gb_w2t [(size_t)NEXP * HID * FDIM];
__device__ __align__(128) __half gb_qkv [(size_t)TOK * 3 * HID];
__device__ __align__(128) __half gb_vT  [(size_t)2 * NHEAD * 64 * SEQ];
__device__ __align__(128) __half gb_ao  [(size_t)TOK * HID];
__device__ __align__(128) __half gb_h2  [(size_t)TOK * HID];
__device__ __align__(128) __half gb_H1  [(size_t)NSLOT * FDIM];
__device__ float g_xattn[(size_t)TOK * HID];
__device__ float g_h2f  [(size_t)TOK * HID];
__device__ float g_Y2   [(size_t)NSLOT * HID];
__device__ int   g_topi [TOK * 2];
__device__ float g_topw [TOK * 2];
__device__ int   g_cnt  [NEXP];
__device__ int   g_offs [NEXP + 1];
__device__ int   g_cur  [NEXP];
__device__ int   g_slottok[NSLOT];
__device__ int   g_slotof [TOK * 2];

// ---------------- PTX helpers ----------------
__device__ __forceinline__ uint32_t s2u(const void* p) {
    uint32_t a;
    asm("{ .reg .u64 t; cvta.to.shared.u64 t, %1; cvt.u32.u64 %0, t; }" : "=r"(a) : "l"(p));
    return a;
}
__device__ __forceinline__ void cpasync16(uint32_t saddr, const void* g) {
    asm volatile("cp.async.cg.shared.global [%0], [%1], 16;" :: "r"(saddr), "l"(g));
}
#define CP_COMMIT() asm volatile("cp.async.commit_group;" ::: "memory")
#define CP_WAIT(n)  asm volatile("cp.async.wait_group %0;" :: "n"(n) : "memory")

__device__ __forceinline__ void ldsm4(uint32_t* r, uint32_t addr) {
    asm volatile("ldmatrix.sync.aligned.m8n8.x4.shared.b16 {%0,%1,%2,%3}, [%4];"
                 : "=r"(r[0]), "=r"(r[1]), "=r"(r[2]), "=r"(r[3]) : "r"(addr));
}
__device__ __forceinline__ void mma16816(float* c, const uint32_t* a, const uint32_t* b) {
    asm volatile("mma.sync.aligned.m16n8k16.row.col.f32.f16.f16.f32 "
                 "{%0,%1,%2,%3}, {%4,%5,%6,%7}, {%8,%9}, {%0,%1,%2,%3};"
                 : "+f"(c[0]), "+f"(c[1]), "+f"(c[2]), "+f"(c[3])
                 : "r"(a[0]), "r"(a[1]), "r"(a[2]), "r"(a[3]), "r"(b[0]), "r"(b[1]));
}
__device__ __forceinline__ float gelu_tanh(float x) {
    float u = 0.7978845608028654f * (x + 0.044715f * x * x * x);
    u = fminf(fmaxf(u, -15.0f), 15.0f);
    float e = __expf(2.0f * u);
    return x * e / (e + 1.0f);
}
__device__ __forceinline__ uint32_t pkh2(float a, float b) {
    __half2 t = __floats2half2_rn(a, b);
    return *(uint32_t*)&t;
}

// ---------------- HMMA GEMM: BK=64 chunks, 3-stage cp.async ring ----------------
// pitch 72 halves (144B) per row — conflict-free for ldsm.
// Invariant: one commit per iteration (empty past tail); CP_WAIT(1) at iter c
// proves chunk c resident; stage (c+2)%3 was last read at iter c-1, protected
// by iter-c's barrier.
#define STAGES3 3
template <int MODE, int NT>
__global__ void __launch_bounds__(256, 2) hgemm(
    const __half* __restrict__ A, const __half* __restrict__ B, void* Cv,
    int M, int N, int K, int lda, int ldb, int ldc,
    const float* __restrict__ bias, const float* __restrict__ res,
    const int* __restrict__ gtok, const int* __restrict__ offs) {
    extern __shared__ __align__(128) char dsm[];
    constexpr uint32_t AST = 128 * 144;
    constexpr uint32_t BST = NT * 144;

    int tid = threadIdx.x, wid = tid >> 5, lid = tid & 31;
    int z = blockIdx.z;
    const __half* Ab = A;
    const __half* Bb = B;
    float* Cf = (float*)Cv;
    __half* Cb = (__half*)Cv;
    const float* biasb = bias;
    int r0 = 0, r1 = M;
    if (MODE == 4 || MODE == 5) {
        r0 = offs[z]; r1 = offs[z + 1];
        Bb = B + (size_t)z * (size_t)N * K;
        biasb = bias + (size_t)z * N;
    }
    int rowBase = r0 + blockIdx.y * 128;
    if (rowBase >= r1) return;
    int n0 = blockIdx.x * NT;

    constexpr int WN = NT / 4;
    constexpr int NTILES = WN / 8;
    int wm = (wid >> 2) * 64;
    int wn = (wid & 3) * WN;

    uint32_t uAs = s2u(dsm);
    uint32_t uBs = uAs + STAGES3 * AST;

    int aRowL = wm + (lid & 15);
    int aColL = (lid >> 4) * 8;
    int bRowL = wn + ((lid >> 4) << 3) + (lid & 7);
    int bColL = ((lid >> 3) & 1) * 8;

    float acc[4][NTILES][4];
#pragma unroll
    for (int i = 0; i < 4; i++)
#pragma unroll
        for (int j = 0; j < NTILES; j++)
#pragma unroll
            for (int q = 0; q < 4; q++) acc[i][j][q] = 0.f;

    int ldRow = tid >> 3, ldCh = tid & 7;
    const __half* aSrc[4];
#pragma unroll
    for (int i = 0; i < 4; i++) {
        int gr = rowBase + ldRow + i * 32;
        if (gr > r1 - 1) gr = r1 - 1;
        aSrc[i] = Ab + (size_t)((MODE == 4) ? gtok[gr] : gr) * lda;
    }

    auto loadStage = [&](int st, int c) {
        int kt = c * 64;
#pragma unroll
        for (int i = 0; i < 4; i++)
            cpasync16(uAs + st * AST + (ldRow + i * 32) * 144 + ldCh * 16,
                      aSrc[i] + kt + ldCh * 8);
#pragma unroll
        for (int i = 0; i < NT / 32; i++) {
            int row = ldRow + i * 32;
            cpasync16(uBs + st * BST + row * 144 + ldCh * 16,
                      Bb + (size_t)(n0 + row) * ldb + kt + ldCh * 8);
        }
    };

    int nk = K / 64;
    loadStage(0, 0); CP_COMMIT();
    loadStage(1, 1); CP_COMMIT();

    int cSt = 0, ldSt = 2;
    for (int c = 0; c < nk; c++) {
        CP_WAIT(1);
        __syncthreads();
        if (c + 2 < nk) loadStage(ldSt, c + 2);
        CP_COMMIT();   // always commit — keeps the wait invariant at the tail
        uint32_t aBase = uAs + cSt * AST;
        uint32_t bBase = uBs + cSt * BST;
#pragma unroll
        for (int ks = 0; ks < 4; ks++) {
            uint32_t afr[4][4];
#pragma unroll
            for (int mt = 0; mt < 4; mt++)
                ldsm4(afr[mt], aBase + (aRowL + mt * 16) * 144 + (ks * 16 + aColL) * 2);
#pragma unroll
            for (int nb = 0; nb < NTILES / 2; nb++) {
                uint32_t bfr[4];
                ldsm4(bfr, bBase + (bRowL + nb * 16) * 144 + (ks * 16 + bColL) * 2);
#pragma unroll
                for (int mt = 0; mt < 4; mt++) {
                    mma16816(acc[mt][2 * nb],     afr[mt], &bfr[0]);
                    mma16816(acc[mt][2 * nb + 1], afr[mt], &bfr[2]);
                }
            }
        }
        cSt  = (cSt  == 2) ? 0 : cSt + 1;
        ldSt = (ldSt == 2) ? 0 : ldSt + 1;
    }

#pragma unroll
    for (int mt = 0; mt < 4; mt++) {
#pragma unroll
        for (int h = 0; h < 2; h++) {
            int row = rowBase + wm + mt * 16 + h * 8 + (lid >> 2);
            if (row >= r1) continue;
#pragma unroll
            for (int nt = 0; nt < NTILES; nt++) {
                float v0 = acc[mt][nt][2 * h], v1 = acc[mt][nt][2 * h + 1];
                int cc = n0 + wn + nt * 8 + 2 * (lid & 3);
                if (MODE == 0) { v0 += bias[cc]; v1 += bias[cc + 1]; }
                if (MODE == 1) {
                    float2 rr = *(const float2*)(res + (size_t)row * ldc + cc);
                    v0 += bias[cc] + rr.x; v1 += bias[cc + 1] + rr.y;
                }
                if (MODE == 4) {
                    v0 = gelu_tanh(v0 + biasb[cc]);
                    v1 = gelu_tanh(v1 + biasb[cc + 1]);
                }
                if (MODE == 5) { v0 += biasb[cc]; v1 += biasb[cc + 1]; }
                if (MODE == 1 || MODE == 5) {
                    *(float2*)(Cf + (size_t)row * ldc + cc) = make_float2(v0, v1);
                } else if (MODE == 0 && cc >= 2 * HID) {
                    int d = cc - 2 * HID;
                    int hh = d >> 6, dd = d & 63;
                    int bb = row >> 11, ss = row & 2047;
                    uint32_t pk = pkh2(v0, v1);
                    __half2 pr = *(__half2*)&pk;
                    __half* vb = gb_vT + ((size_t)(bb * NHEAD + hh) * 64 + dd) * SEQ + ss;
                    vb[0]   = __low2half(pr);
                    vb[SEQ] = __high2half(pr);
                } else {
                    *(uint32_t*)(Cb + (size_t)row * ldc + cc) = pkh2(v0, v1);
                }
            }
        }
    }
}

// ---------------- fused flash attention (occ 2) ----------------
__global__ void __launch_bounds__(256, 2) flash_k(const __half* __restrict__ qkv,
                                                  const __half* __restrict__ vT,
                                                  __half* __restrict__ ao) {
    extern __shared__ char dyn[];
    constexpr uint32_t QBYTES = 128 * 72 * 2;
    constexpr uint32_t KST    = 128 * 72 * 2;
    constexpr uint32_t VST    = 64 * 136 * 2;
    char* sQ = dyn;
    char* sK = dyn + QBYTES;
    char* sV = dyn + QBYTES + 2 * KST;

    int tid = threadIdx.x, wid = tid >> 5, lid = tid & 31;
    int qt = blockIdx.x, bh = blockIdx.y;
    int b = bh >> 4, h = bh & 15;
    int q0 = qt * 128;
    const __half* Qg = qkv + (size_t)b * SEQ * 3 * HID + h * 64;
    const __half* Kg = qkv + (size_t)b * SEQ * 3 * HID + HID + h * 64;
    const __half* Vt = vT + (size_t)bh * 64 * SEQ;

    uint32_t uQ = s2u(sQ), uK = s2u(sK), uV = s2u(sV);

#pragma unroll
    for (int i = 0; i < 4; i++) {
        int idx = tid + i * 256;
        int row = idx >> 3, ch = idx & 7;
        cpasync16(uQ + row * 144 + ch * 16, Qg + (size_t)(q0 + row) * 3 * HID + ch * 8);
    }
    auto loadKV = [&](int st, int kt) {
#pragma unroll
        for (int i = 0; i < 4; i++) {
            int idx = tid + i * 256;
            int row = idx >> 3, ch = idx & 7;
            cpasync16(uK + st * KST + row * 144 + ch * 16,
                      Kg + (size_t)(kt * 128 + row) * 3 * HID + ch * 8);
        }
#pragma unroll
        for (int i = 0; i < 4; i++) {
            int idx = tid + i * 256;
            int row = idx >> 4, ch = idx & 15;
            cpasync16(uV + st * VST + row * 272 + ch * 16,
                      Vt + (size_t)row * SEQ + kt * 128 + ch * 8);
        }
    };
    loadKV(0, 0);
    CP_COMMIT();

    float oacc[8][4];
#pragma unroll
    for (int j = 0; j < 8; j++)
#pragma unroll
        for (int q = 0; q < 4; q++) oacc[j][q] = 0.f;
    float m0 = -1e30f, m1 = -1e30f, l0 = 0.f, l1 = 0.f;

    int aRowL = wid * 16 + (lid & 15);
    int aColL = (lid >> 4) * 8;
    int bRowL = ((lid >> 4) << 3) + (lid & 7);
    int bColL = ((lid >> 3) & 1) * 8;

    for (int kt = 0; kt < SEQ / 128; kt++) {
        if (kt + 1 < SEQ / 128) { loadKV((kt + 1) & 1, kt + 1); CP_COMMIT(); CP_WAIT(1); }
        else CP_WAIT(0);
        __syncthreads();
        int st = kt & 1;
        uint32_t kBase = uK + st * KST;
        uint32_t vBase = uV + st * VST;

        float sacc[16][4];
#pragma unroll
        for (int t = 0; t < 16; t++)
#pragma unroll
            for (int q = 0; q < 4; q++) sacc[t][q] = 0.f;

#pragma unroll
        for (int ks = 0; ks < 4; ks++) {
            uint32_t afr[4];
            ldsm4(afr, uQ + aRowL * 144 + (ks * 16 + aColL) * 2);
#pragma unroll
            for (int nb = 0; nb < 8; nb++) {
                uint32_t bfr[4];
                ldsm4(bfr, kBase + (nb * 16 + bRowL) * 144 + (ks * 16 + bColL) * 2);
                mma16816(sacc[2 * nb],     afr, &bfr[0]);
                mma16816(sacc[2 * nb + 1], afr, &bfr[2]);
            }
        }

        float tm0 = -1e30f, tm1 = -1e30f;
#pragma unroll
        for (int t = 0; t < 16; t++) {
            sacc[t][0] *= 0.125f; sacc[t][1] *= 0.125f;
            sacc[t][2] *= 0.125f; sacc[t][3] *= 0.125f;
            tm0 = fmaxf(tm0, fmaxf(sacc[t][0], sacc[t][1]));
            tm1 = fmaxf(tm1, fmaxf(sacc[t][2], sacc[t][3]));
        }
        tm0 = fmaxf(tm0, __shfl_xor_sync(0xffffffffu, tm0, 1));
        tm0 = fmaxf(tm0, __shfl_xor_sync(0xffffffffu, tm0, 2));
        tm1 = fmaxf(tm1, __shfl_xor_sync(0xffffffffu, tm1, 1));
        tm1 = fmaxf(tm1, __shfl_xor_sync(0xffffffffu, tm1, 2));
        float nm0 = fmaxf(m0, tm0), nm1 = fmaxf(m1, tm1);
        float f0 = __expf(m0 - nm0), f1 = __expf(m1 - nm1);
        m0 = nm0; m1 = nm1;
        float rs0 = 0.f, rs1 = 0.f;
#pragma unroll
        for (int t = 0; t < 16; t++) {
            sacc[t][0] = __expf(sacc[t][0] - nm0);
            sacc[t][1] = __expf(sacc[t][1] - nm0);
            sacc[t][2] = __expf(sacc[t][2] - nm1);
            sacc[t][3] = __expf(sacc[t][3] - nm1);
            rs0 += sacc[t][0] + sacc[t][1];
            rs1 += sacc[t][2] + sacc[t][3];
        }
        rs0 += __shfl_xor_sync(0xffffffffu, rs0, 1);
        rs0 += __shfl_xor_sync(0xffffffffu, rs0, 2);
        rs1 += __shfl_xor_sync(0xffffffffu, rs1, 1);
        rs1 += __shfl_xor_sync(0xffffffffu, rs1, 2);
        l0 = l0 * f0 + rs0;
        l1 = l1 * f1 + rs1;
#pragma unroll
        for (int j = 0; j < 8; j++) {
            oacc[j][0] *= f0; oacc[j][1] *= f0;
            oacc[j][2] *= f1; oacc[j][3] *= f1;
        }

#pragma unroll
        for (int ks = 0; ks < 8; ks++) {
            uint32_t pa[4];
            pa[0] = pkh2(sacc[2 * ks][0],     sacc[2 * ks][1]);
            pa[1] = pkh2(sacc[2 * ks][2],     sacc[2 * ks][3]);
            pa[2] = pkh2(sacc[2 * ks + 1][0], sacc[2 * ks + 1][1]);
            pa[3] = pkh2(sacc[2 * ks + 1][2], sacc[2 * ks + 1][3]);
#pragma unroll
            for (int nb = 0; nb < 4; nb++) {
                uint32_t bfr[4];
                ldsm4(bfr, vBase + (nb * 16 + bRowL) * 272 + (ks * 16 + bColL) * 2);
                mma16816(oacc[2 * nb],     pa, &bfr[0]);
                mma16816(oacc[2 * nb + 1], pa, &bfr[2]);
            }
        }
        __syncthreads();
    }

    float i0 = 1.0f / l0, i1 = 1.0f / l1;
    int row = q0 + wid * 16 + (lid >> 2);
    __half* d0 = ao + ((size_t)b * SEQ + row) * HID + h * 64;
    __half* d1 = ao + ((size_t)b * SEQ + row + 8) * HID + h * 64;
#pragma unroll
    for (int j = 0; j < 8; j++) {
        int cc = j * 8 + (lid & 3) * 2;
        *(uint32_t*)(d0 + cc) = pkh2(oacc[j][0] * i0, oacc[j][1] * i0);
        *(uint32_t*)(d1 + cc) = pkh2(oacc[j][2] * i1, oacc[j][3] * i1);
    }
}

// ---------------- support kernels ----------------
__global__ void __launch_bounds__(256) f2h_k(const float* __restrict__ in, __half* __restrict__ outp, int n4) {
    int i = blockIdx.x * 256 + threadIdx.x;
    if (i >= n4) return;
    float4 v = ((const float4*)in)[i];
    ((uint2*)outp)[i] = make_uint2(pkh2(v.x, v.y), pkh2(v.z, v.w));
}

__global__ void tconv_k(const float* __restrict__ in, __half* __restrict__ outp, int R, int C) {
    __shared__ float t[32][33];
    in += (size_t)blockIdx.z * R * C;
    outp += (size_t)blockIdx.z * R * C;
    int x = blockIdx.x * 32 + threadIdx.x;
    int y0 = blockIdx.y * 32;
#pragma unroll
    for (int j = 0; j < 32; j += 8)
        t[threadIdx.y + j][threadIdx.x] = in[(size_t)(y0 + threadIdx.y + j) * C + x];
    __syncthreads();
    int ox = y0 + threadIdx.x;
    int oy0 = blockIdx.x * 32;
#pragma unroll
    for (int j = 0; j < 32; j += 8)
        outp[(size_t)(oy0 + threadIdx.y + j) * R + ox] = __float2half_rn(t[threadIdx.x][threadIdx.y + j]);
}

template <bool BOTH>
__global__ void __launch_bounds__(256) ln_k(const float* __restrict__ x, const float* __restrict__ g,
                                            const float* __restrict__ bta,
                                            __half* __restrict__ ob, float* __restrict__ of) {
    __shared__ float red[16], fin[2];
    int tid = threadIdx.x;
    size_t row = blockIdx.x;
    float4 v = ((const float4*)(x + row * HID))[tid];
    float s = v.x + v.y + v.z + v.w;
    float q = v.x * v.x + v.y * v.y + v.z * v.z + v.w * v.w;
#pragma unroll
    for (int o = 16; o; o >>= 1) {
        s += __shfl_xor_sync(0xffffffffu, s, o);
        q += __shfl_xor_sync(0xffffffffu, q, o);
    }
    if ((tid & 31) == 0) { red[tid >> 5] = s; red[8 + (tid >> 5)] = q; }
    __syncthreads();
    if (tid < 8) {
        s = red[tid]; q = red[8 + tid];
#pragma unroll
        for (int o = 4; o; o >>= 1) {
            s += __shfl_xor_sync(0xffu, s, o);
            q += __shfl_xor_sync(0xffu, q, o);
        }
        if (tid == 0) {
            float mu = s * (1.0f / HID);
            fin[0] = mu;
            fin[1] = rsqrtf(q * (1.0f / HID) - mu * mu + 1e-5f);
        }
    }
    __syncthreads();
    float mu = fin[0], rstd = fin[1];
    float4 gv = ((const float4*)g)[tid];
    float4 bv = ((const float4*)bta)[tid];
    float4 o;
    o.x = (v.x - mu) * rstd * gv.x + bv.x;
    o.y = (v.y - mu) * rstd * gv.y + bv.y;
    o.z = (v.z - mu) * rstd * gv.z + bv.z;
    o.w = (v.w - mu) * rstd * gv.w + bv.w;
    ((uint2*)(ob + row * HID))[tid] = make_uint2(pkh2(o.x, o.y), pkh2(o.z, o.w));
    if (BOTH) ((float4*)(of + row * HID))[tid] = o;
}

__global__ void __launch_bounds__(256) gate_k(const float* __restrict__ Wg) {
    int warp = (blockIdx.x * 256 + threadIdx.x) >> 5;
    int lane = threadIdx.x & 31;
    if (warp >= TOK) return;
    const float* xr = g_h2f + (size_t)warp * HID;
    float acc[8] = {0, 0, 0, 0, 0, 0, 0, 0};
    for (int hh = lane; hh < HID; hh += 32) {
        float xv = xr[hh];
        float4 w0 = *(const float4*)(Wg + hh * 8);
        float4 w1 = *(const float4*)(Wg + hh * 8 + 4);
        acc[0] += xv * w0.x; acc[1] += xv * w0.y; acc[2] += xv * w0.z; acc[3] += xv * w0.w;
        acc[4] += xv * w1.x; acc[5] += xv * w1.y; acc[6] += xv * w1.z; acc[7] += xv * w1.w;
    }
#pragma unroll
    for (int o = 16; o; o >>= 1)
#pragma unroll
        for (int e = 0; e < 8; e++) acc[e] += __shfl_xor_sync(0xffffffffu, acc[e], o);
    if (lane == 0) {
        int i0 = 0; float v0 = acc[0];
#pragma unroll
        for (int e = 1; e < 8; e++) if (acc[e] > v0) { v0 = acc[e]; i0 = e; }
        int i1 = -1; float v1 = -3.4e38f;
#pragma unroll
        for (int e = 0; e < 8; e++) if (e != i0 && acc[e] > v1) { v1 = acc[e]; i1 = e; }
        float w0 = 1.0f / (1.0f + __expf(v1 - v0));
        g_topi[2 * warp] = i0; g_topi[2 * warp + 1] = i1;
        g_topw[2 * warp] = w0; g_topw[2 * warp + 1] = 1.0f - w0;
        atomicAdd(&g_cnt[i0], 1);
        atomicAdd(&g_cnt[i1], 1);
    }
}

__global__ void __launch_bounds__(1024) route_k() {
    if (threadIdx.x == 0) {
        g_offs[0] = 0;
        for (int e = 0; e < NEXP; e++) g_offs[e + 1] = g_offs[e] + g_cnt[e];
    }
    __syncthreads();
    for (int idx = threadIdx.x; idx < TOK * 2; idx += 1024) {
        int e = g_topi[idx];
        int pos = atomicAdd(&g_cur[e], 1);
        int slot = g_offs[e] + pos;
        g_slottok[slot] = idx >> 1;
        g_slotof[idx] = slot;
    }
}

__global__ void __launch_bounds__(256) combine_k(float* __restrict__ outp) {
    int t = blockIdx.x;
    int j = threadIdx.x;
    float w0 = g_topw[2 * t], w1 = g_topw[2 * t + 1];
    size_t s0 = g_slotof[2 * t], s1 = g_slotof[2 * t + 1];
    float4 r  = ((const float4*)(g_xattn + (size_t)t * HID))[j];
    float4 y0 = ((const float4*)(g_Y2 + s0 * HID))[j];
    float4 y1 = ((const float4*)(g_Y2 + s1 * HID))[j];
    r.x += w0 * y0.x + w1 * y1.x;
    r.y += w0 * y0.y + w1 * y1.y;
    r.z += w0 * y0.z + w1 * y1.z;
    r.w += w0 * y0.w + w1 * y1.w;
    ((float4*)(outp + (size_t)t * HID))[j] = r;
}

#define SYM(p, s) void* p; cudaGetSymbolAddress(&p, s)

extern "C" void kernel_launch(void* const* d_in, const int* in_sizes, int n_in,
                              void* d_out, int out_size) {
    const float* x     = (const float*)d_in[0];
    const float* ln1_g = (const float*)d_in[1];
    const float* ln1_b = (const float*)d_in[2];
    const float* qkv_w = (const float*)d_in[3];
    const float* qkv_b = (const float*)d_in[4];
    const float* out_w = (const float*)d_in[5];
    const float* out_b = (const float*)d_in[6];
    const float* ln2_g = (const float*)d_in[7];
    const float* ln2_b = (const float*)d_in[8];
    const float* Wg    = (const float*)d_in[9];
    const float* W1    = (const float*)d_in[10];
    const float* b1    = (const float*)d_in[11];
    const float* W2    = (const float*)d_in[12];
    const float* b2    = (const float*)d_in[13];
    float* outp = (float*)d_out;

    SYM(p_hln, gb_hln);   SYM(p_qkvw, gb_qkvw); SYM(p_outw, gb_outw);
    SYM(p_w1t, gb_w1t);   SYM(p_w2t, gb_w2t);   SYM(p_qkv, gb_qkv);
    SYM(p_vT, gb_vT);     SYM(p_ao, gb_ao);     SYM(p_h2b, gb_h2);
    SYM(p_H1, gb_H1);     SYM(p_xattn, g_xattn); SYM(p_h2f, g_h2f);
    SYM(p_Y2, g_Y2);      SYM(p_cnt, g_cnt);    SYM(p_cur, g_cur);
    SYM(p_slottok, g_slottok); SYM(p_offs, g_offs);

    constexpr int GEMM_SMEM = STAGES3 * (128 + 128) * 144;  // 110592
    cudaFuncSetAttribute(hgemm<0, 128>, cudaFuncAttributeMaxDynamicSharedMemorySize, GEMM_SMEM);
    cudaFuncSetAttribute(hgemm<1, 128>, cudaFuncAttributeMaxDynamicSharedMemorySize, GEMM_SMEM);
    cudaFuncSetAttribute(hgemm<4, 128>, cudaFuncAttributeMaxDynamicSharedMemorySize, GEMM_SMEM);
    cudaFuncSetAttribute(hgemm<5, 128>, cudaFuncAttributeMaxDynamicSharedMemorySize, GEMM_SMEM);
    constexpr int FLASH_SMEM = (128 * 72 * 2) * 3 + (64 * 136 * 2) * 2;  // 90112
    cudaFuncSetAttribute(flash_k, cudaFuncAttributeMaxDynamicSharedMemorySize, FLASH_SMEM);

    cudaStream_t s2;
    cudaStreamCreateWithFlags(&s2, cudaStreamNonBlocking);
    cudaEvent_t evFork, evQkvw, evJoin;
    cudaEventCreateWithFlags(&evFork, cudaEventDisableTiming);
    cudaEventCreateWithFlags(&evQkvw, cudaEventDisableTiming);
    cudaEventCreateWithFlags(&evJoin, cudaEventDisableTiming);

    cudaEventRecord(evFork, 0);
    cudaStreamWaitEvent(s2, evFork, 0);

    dim3 tb(32, 8);
    // side stream: qkv_w convert first (joined early), then the rest
    f2h_k<<<(3 * HID * HID / 4 + 255) / 256, 256, 0, s2>>>(qkv_w, (__half*)p_qkvw, 3 * HID * HID / 4);
    cudaEventRecord(evQkvw, s2);
    tconv_k<<<dim3(FDIM / 32, HID / 32, NEXP), tb, 0, s2>>>(W1, (__half*)p_w1t, HID, FDIM);
    tconv_k<<<dim3(HID / 32, FDIM / 32, NEXP), tb, 0, s2>>>(W2, (__half*)p_w2t, FDIM, HID);
    f2h_k<<<(HID * HID / 4 + 255) / 256, 256, 0, s2>>>(out_w, (__half*)p_outw, HID * HID / 4);
    cudaMemsetAsync(p_cnt, 0, NEXP * sizeof(int), s2);
    cudaMemsetAsync(p_cur, 0, NEXP * sizeof(int), s2);
    cudaEventRecord(evJoin, s2);

    // main stream: LN1 overlaps the qkv_w conversion
    ln_k<false><<<TOK, 256>>>(x, ln1_g, ln1_b, (__half*)p_hln, nullptr);
    cudaStreamWaitEvent(0, evQkvw, 0);

    hgemm<0, 128><<<dim3(3 * HID / 128, TOK / 128, 1), 256, GEMM_SMEM>>>(
        (const __half*)p_hln, (const __half*)p_qkvw, p_qkv,
        TOK, 3 * HID, HID, HID, HID, 3 * HID, qkv_b, nullptr, nullptr, nullptr);

    flash_k<<<dim3(SEQ / 128, 2 * NHEAD), 256, FLASH_SMEM>>>(
        (const __half*)p_qkv, (const __half*)p_vT, (__half*)p_ao);

    cudaStreamWaitEvent(0, evJoin, 0);

    hgemm<1, 128><<<dim3(HID / 128, TOK / 128, 1), 256, GEMM_SMEM>>>(
        (const __half*)p_ao, (const __half*)p_outw, p_xattn,
        TOK, HID, HID, HID, HID, HID, out_b, x, nullptr, nullptr);

    ln_k<true><<<TOK, 256>>>((const float*)p_xattn, ln2_g, ln2_b,
                             (__half*)p_h2b, (float*)p_h2f);

    gate_k<<<TOK / 8, 256>>>(Wg);
    route_k<<<1, 1024>>>();

    hgemm<4, 128><<<dim3(FDIM / 128, NSLOT / 128, NEXP), 256, GEMM_SMEM>>>(
        (const __half*)p_h2b, (const __half*)p_w1t, p_H1,
        0, FDIM, HID, HID, HID, FDIM, b1, nullptr, (const int*)p_slottok, (const int*)p_offs);

    hgemm<5, 128><<<dim3(HID / 128, NSLOT / 128, NEXP), 256, GEMM_SMEM>>>(
        (const __half*)p_H1, (const __half*)p_w2t, p_Y2,
        0, HID, FDIM, FDIM, FDIM, HID, b2, nullptr, nullptr, (const int*)p_offs);

    combine_k<<<TOK, 256>>>(outp);

    cudaStreamDestroy(s2);
    cudaEventDestroy(evFork);
    cudaEventDestroy(evQkvw);
    cudaEventDestroy(evJoin);
}

// round 17
// speedup vs baseline: 1.0988x; 1.0129x over previous
#include <cuda_runtime.h>
#include <cuda_fp16.h>
#include <cstdint>
#include <cstddef>

#define TOK   4096
#define SEQ   2048
#define HID   1024
#define NHEAD 16
#define NEXP  8
#define FDIM  4096
#define NSLOT 8192

// ---------------- scratch ----------------
__device__ __align__(128) __half gb_hln [(size_t)TOK * HID];
__device__ __align__(128) __half gb_qkvw[(size_t)3 * HID * HID];
__device__ __align__(128) __half gb_outw[(size_t)HID * HID];
__device__ __align__(128) __half gb_w1t [(size_t)NEXP * FDIM * HID];
__device__ __align__(128) __half gb_w2t [(size_t)NEXP * HID * FDIM];
__device__ __align__(128) __half gb_qkv [(size_t)TOK * 3 * HID];
__device__ __align__(128) __half gb_vT  [(size_t)2 * NHEAD * 64 * SEQ];
__device__ __align__(128) __half gb_ao  [(size_t)TOK * HID];
__device__ __align__(128) __half gb_h2  [(size_t)TOK * HID];
__device__ __align__(128) __half gb_H1  [(size_t)NSLOT * FDIM];
__device__ float g_xattn[(size_t)TOK * HID];
__device__ float g_h2f  [(size_t)TOK * HID];
__device__ float g_Y2   [(size_t)NSLOT * HID];
__device__ int   g_topi [TOK * 2];
__device__ float g_topw [TOK * 2];
__device__ int   g_cnt  [NEXP];
__device__ int   g_offs [NEXP + 1];
__device__ int   g_cur  [NEXP];
__device__ int   g_slottok[NSLOT];
__device__ int   g_slotof [TOK * 2];

// ---------------- PTX helpers ----------------
__device__ __forceinline__ uint32_t s2u(const void* p) {
    uint32_t a;
    asm("{ .reg .u64 t; cvta.to.shared.u64 t, %1; cvt.u32.u64 %0, t; }" : "=r"(a) : "l"(p));
    return a;
}
__device__ __forceinline__ void cpasync16(uint32_t saddr, const void* g) {
    asm volatile("cp.async.cg.shared.global [%0], [%1], 16;" :: "r"(saddr), "l"(g));
}
#define CP_COMMIT() asm volatile("cp.async.commit_group;" ::: "memory")
#define CP_WAIT(n)  asm volatile("cp.async.wait_group %0;" :: "n"(n) : "memory")

__device__ __forceinline__ void ldsm4(uint32_t* r, uint32_t addr) {
    asm volatile("ldmatrix.sync.aligned.m8n8.x4.shared.b16 {%0,%1,%2,%3}, [%4];"
                 : "=r"(r[0]), "=r"(r[1]), "=r"(r[2]), "=r"(r[3]) : "r"(addr));
}
__device__ __forceinline__ void mma16816(float* c, const uint32_t* a, const uint32_t* b) {
    asm volatile("mma.sync.aligned.m16n8k16.row.col.f32.f16.f16.f32 "
                 "{%0,%1,%2,%3}, {%4,%5,%6,%7}, {%8,%9}, {%0,%1,%2,%3};"
                 : "+f"(c[0]), "+f"(c[1]), "+f"(c[2]), "+f"(c[3])
                 : "r"(a[0]), "r"(a[1]), "r"(a[2]), "r"(a[3]), "r"(b[0]), "r"(b[1]));
}
__device__ __forceinline__ float gelu_tanh(float x) {
    float u = 0.7978845608028654f * (x + 0.044715f * x * x * x);
    u = fminf(fmaxf(u, -15.0f), 15.0f);
    float e = __expf(2.0f * u);
    return x * e / (e + 1.0f);
}
__device__ __forceinline__ uint32_t pkh2(float a, float b) {
    __half2 t = __floats2half2_rn(a, b);
    return *(uint32_t*)&t;
}

// ---------------- HMMA GEMM: BK=64 chunks, 3-stage cp.async ring ----------------
// pitch 72 halves (144B) per row — conflict-free for ldsm.
// Invariant: one commit per iteration (empty past tail); CP_WAIT(1) at iter c
// proves chunk c resident; stage (c+2)%3 was last read at iter c-1, protected
// by iter-c's barrier.
#define STAGES3 3
template <int MODE, int NT>
__global__ void __launch_bounds__(256, 2) hgemm(
    const __half* __restrict__ A, const __half* __restrict__ B, void* Cv,
    int M, int N, int K, int lda, int ldb, int ldc,
    const float* __restrict__ bias, const float* __restrict__ res,
    const int* __restrict__ gtok, const int* __restrict__ offs) {
    extern __shared__ __align__(128) char dsm[];
    constexpr uint32_t AST = 128 * 144;
    constexpr uint32_t BST = NT * 144;

    int tid = threadIdx.x, wid = tid >> 5, lid = tid & 31;
    int z = blockIdx.z;
    const __half* Ab = A;
    const __half* Bb = B;
    float* Cf = (float*)Cv;
    __half* Cb = (__half*)Cv;
    const float* biasb = bias;
    int r0 = 0, r1 = M;
    if (MODE == 4 || MODE == 5) {
        r0 = offs[z]; r1 = offs[z + 1];
        Bb = B + (size_t)z * (size_t)N * K;
        biasb = bias + (size_t)z * N;
    }
    int rowBase = r0 + blockIdx.y * 128;
    if (rowBase >= r1) return;
    int n0 = blockIdx.x * NT;

    constexpr int WN = NT / 4;
    constexpr int NTILES = WN / 8;
    int wm = (wid >> 2) * 64;
    int wn = (wid & 3) * WN;

    uint32_t uAs = s2u(dsm);
    uint32_t uBs = uAs + STAGES3 * AST;

    int aRowL = wm + (lid & 15);
    int aColL = (lid >> 4) * 8;
    int bRowL = wn + ((lid >> 4) << 3) + (lid & 7);
    int bColL = ((lid >> 3) & 1) * 8;

    float acc[4][NTILES][4];
#pragma unroll
    for (int i = 0; i < 4; i++)
#pragma unroll
        for (int j = 0; j < NTILES; j++)
#pragma unroll
            for (int q = 0; q < 4; q++) acc[i][j][q] = 0.f;

    int ldRow = tid >> 3, ldCh = tid & 7;
    const __half* aSrc[4];
#pragma unroll
    for (int i = 0; i < 4; i++) {
        int gr = rowBase + ldRow + i * 32;
        if (gr > r1 - 1) gr = r1 - 1;
        aSrc[i] = Ab + (size_t)((MODE == 4) ? gtok[gr] : gr) * lda;
    }

    auto loadStage = [&](int st, int c) {
        int kt = c * 64;
#pragma unroll
        for (int i = 0; i < 4; i++)
            cpasync16(uAs + st * AST + (ldRow + i * 32) * 144 + ldCh * 16,
                      aSrc[i] + kt + ldCh * 8);
#pragma unroll
        for (int i = 0; i < NT / 32; i++) {
            int row = ldRow + i * 32;
            cpasync16(uBs + st * BST + row * 144 + ldCh * 16,
                      Bb + (size_t)(n0 + row) * ldb + kt + ldCh * 8);
        }
    };

    int nk = K / 64;
    loadStage(0, 0); CP_COMMIT();
    loadStage(1, 1); CP_COMMIT();

    int cSt = 0, ldSt = 2;
    for (int c = 0; c < nk; c++) {
        CP_WAIT(1);
        __syncthreads();
        if (c + 2 < nk) loadStage(ldSt, c + 2);
        CP_COMMIT();   // always commit — keeps the wait invariant at the tail
        uint32_t aBase = uAs + cSt * AST;
        uint32_t bBase = uBs + cSt * BST;
#pragma unroll
        for (int ks = 0; ks < 4; ks++) {
            uint32_t afr[4][4];
#pragma unroll
            for (int mt = 0; mt < 4; mt++)
                ldsm4(afr[mt], aBase + (aRowL + mt * 16) * 144 + (ks * 16 + aColL) * 2);
#pragma unroll
            for (int nb = 0; nb < NTILES / 2; nb++) {
                uint32_t bfr[4];
                ldsm4(bfr, bBase + (bRowL + nb * 16) * 144 + (ks * 16 + bColL) * 2);
#pragma unroll
                for (int mt = 0; mt < 4; mt++) {
                    mma16816(acc[mt][2 * nb],     afr[mt], &bfr[0]);
                    mma16816(acc[mt][2 * nb + 1], afr[mt], &bfr[2]);
                }
            }
        }
        cSt  = (cSt  == 2) ? 0 : cSt + 1;
        ldSt = (ldSt == 2) ? 0 : ldSt + 1;
    }

#pragma unroll
    for (int mt = 0; mt < 4; mt++) {
#pragma unroll
        for (int h = 0; h < 2; h++) {
            int row = rowBase + wm + mt * 16 + h * 8 + (lid >> 2);
            if (row >= r1) continue;
#pragma unroll
            for (int nt = 0; nt < NTILES; nt++) {
                float v0 = acc[mt][nt][2 * h], v1 = acc[mt][nt][2 * h + 1];
                int cc = n0 + wn + nt * 8 + 2 * (lid & 3);
                if (MODE == 0) { v0 += bias[cc]; v1 += bias[cc + 1]; }
                if (MODE == 1) {
                    float2 rr = *(const float2*)(res + (size_t)row * ldc + cc);
                    v0 += bias[cc] + rr.x; v1 += bias[cc + 1] + rr.y;
                }
                if (MODE == 4) {
                    v0 = gelu_tanh(v0 + biasb[cc]);
                    v1 = gelu_tanh(v1 + biasb[cc + 1]);
                }
                if (MODE == 5) { v0 += biasb[cc]; v1 += biasb[cc + 1]; }
                if (MODE == 1 || MODE == 5) {
                    *(float2*)(Cf + (size_t)row * ldc + cc) = make_float2(v0, v1);
                } else if (MODE == 0 && cc >= 2 * HID) {
                    int d = cc - 2 * HID;
                    int hh = d >> 6, dd = d & 63;
                    int bb = row >> 11, ss = row & 2047;
                    uint32_t pk = pkh2(v0, v1);
                    __half2 pr = *(__half2*)&pk;
                    __half* vb = gb_vT + ((size_t)(bb * NHEAD + hh) * 64 + dd) * SEQ + ss;
                    vb[0]   = __low2half(pr);
                    vb[SEQ] = __high2half(pr);
                } else {
                    *(uint32_t*)(Cb + (size_t)row * ldc + cc) = pkh2(v0, v1);
                }
            }
        }
    }
}

// ---------------- fused flash attention (occ 2) ----------------
__global__ void __launch_bounds__(256, 2) flash_k(const __half* __restrict__ qkv,
                                                  const __half* __restrict__ vT,
                                                  __half* __restrict__ ao) {
    extern __shared__ char dyn[];
    constexpr uint32_t QBYTES = 128 * 72 * 2;
    constexpr uint32_t KST    = 128 * 72 * 2;
    constexpr uint32_t VST    = 64 * 136 * 2;
    char* sQ = dyn;
    char* sK = dyn + QBYTES;
    char* sV = dyn + QBYTES + 2 * KST;

    int tid = threadIdx.x, wid = tid >> 5, lid = tid & 31;
    int qt = blockIdx.x, bh = blockIdx.y;
    int b = bh >> 4, h = bh & 15;
    int q0 = qt * 128;
    const __half* Qg = qkv + (size_t)b * SEQ * 3 * HID + h * 64;
    const __half* Kg = qkv + (size_t)b * SEQ * 3 * HID + HID + h * 64;
    const __half* Vt = vT + (size_t)bh * 64 * SEQ;

    uint32_t uQ = s2u(sQ), uK = s2u(sK), uV = s2u(sV);

#pragma unroll
    for (int i = 0; i < 4; i++) {
        int idx = tid + i * 256;
        int row = idx >> 3, ch = idx & 7;
        cpasync16(uQ + row * 144 + ch * 16, Qg + (size_t)(q0 + row) * 3 * HID + ch * 8);
    }
    auto loadKV = [&](int st, int kt) {
#pragma unroll
        for (int i = 0; i < 4; i++) {
            int idx = tid + i * 256;
            int row = idx >> 3, ch = idx & 7;
            cpasync16(uK + st * KST + row * 144 + ch * 16,
                      Kg + (size_t)(kt * 128 + row) * 3 * HID + ch * 8);
        }
#pragma unroll
        for (int i = 0; i < 4; i++) {
            int idx = tid + i * 256;
            int row = idx >> 4, ch = idx & 15;
            cpasync16(uV + st * VST + row * 272 + ch * 16,
                      Vt + (size_t)row * SEQ + kt * 128 + ch * 8);
        }
    };
    loadKV(0, 0);
    CP_COMMIT();

    float oacc[8][4];
#pragma unroll
    for (int j = 0; j < 8; j++)
#pragma unroll
        for (int q = 0; q < 4; q++) oacc[j][q] = 0.f;
    float m0 = -1e30f, m1 = -1e30f, l0 = 0.f, l1 = 0.f;

    int aRowL = wid * 16 + (lid & 15);
    int aColL = (lid >> 4) * 8;
    int bRowL = ((lid >> 4) << 3) + (lid & 7);
    int bColL = ((lid >> 3) & 1) * 8;

    for (int kt = 0; kt < SEQ / 128; kt++) {
        if (kt + 1 < SEQ / 128) { loadKV((kt + 1) & 1, kt + 1); CP_COMMIT(); CP_WAIT(1); }
        else CP_WAIT(0);
        __syncthreads();
        int st = kt & 1;
        uint32_t kBase = uK + st * KST;
        uint32_t vBase = uV + st * VST;

        float sacc[16][4];
#pragma unroll
        for (int t = 0; t < 16; t++)
#pragma unroll
            for (int q = 0; q < 4; q++) sacc[t][q] = 0.f;

#pragma unroll
        for (int ks = 0; ks < 4; ks++) {
            uint32_t afr[4];
            ldsm4(afr, uQ + aRowL * 144 + (ks * 16 + aColL) * 2);
#pragma unroll
            for (int nb = 0; nb < 8; nb++) {
                uint32_t bfr[4];
                ldsm4(bfr, kBase + (nb * 16 + bRowL) * 144 + (ks * 16 + bColL) * 2);
                mma16816(sacc[2 * nb],     afr, &bfr[0]);
                mma16816(sacc[2 * nb + 1], afr, &bfr[2]);
            }
        }

        float tm0 = -1e30f, tm1 = -1e30f;
#pragma unroll
        for (int t = 0; t < 16; t++) {
            sacc[t][0] *= 0.125f; sacc[t][1] *= 0.125f;
            sacc[t][2] *= 0.125f; sacc[t][3] *= 0.125f;
            tm0 = fmaxf(tm0, fmaxf(sacc[t][0], sacc[t][1]));
            tm1 = fmaxf(tm1, fmaxf(sacc[t][2], sacc[t][3]));
        }
        tm0 = fmaxf(tm0, __shfl_xor_sync(0xffffffffu, tm0, 1));
        tm0 = fmaxf(tm0, __shfl_xor_sync(0xffffffffu, tm0, 2));
        tm1 = fmaxf(tm1, __shfl_xor_sync(0xffffffffu, tm1, 1));
        tm1 = fmaxf(tm1, __shfl_xor_sync(0xffffffffu, tm1, 2));
        float nm0 = fmaxf(m0, tm0), nm1 = fmaxf(m1, tm1);
        float f0 = __expf(m0 - nm0), f1 = __expf(m1 - nm1);
        m0 = nm0; m1 = nm1;
        float rs0 = 0.f, rs1 = 0.f;
#pragma unroll
        for (int t = 0; t < 16; t++) {
            sacc[t][0] = __expf(sacc[t][0] - nm0);
            sacc[t][1] = __expf(sacc[t][1] - nm0);
            sacc[t][2] = __expf(sacc[t][2] - nm1);
            sacc[t][3] = __expf(sacc[t][3] - nm1);
            rs0 += sacc[t][0] + sacc[t][1];
            rs1 += sacc[t][2] + sacc[t][3];
        }
        rs0 += __shfl_xor_sync(0xffffffffu, rs0, 1);
        rs0 += __shfl_xor_sync(0xffffffffu, rs0, 2);
        rs1 += __shfl_xor_sync(0xffffffffu, rs1, 1);
        rs1 += __shfl_xor_sync(0xffffffffu, rs1, 2);
        l0 = l0 * f0 + rs0;
        l1 = l1 * f1 + rs1;
#pragma unroll
        for (int j = 0; j < 8; j++) {
            oacc[j][0] *= f0; oacc[j][1] *= f0;
            oacc[j][2] *= f1; oacc[j][3] *= f1;
        }

#pragma unroll
        for (int ks = 0; ks < 8; ks++) {
            uint32_t pa[4];
            pa[0] = pkh2(sacc[2 * ks][0],     sacc[2 * ks][1]);
            pa[1] = pkh2(sacc[2 * ks][2],     sacc[2 * ks][3]);
            pa[2] = pkh2(sacc[2 * ks + 1][0], sacc[2 * ks + 1][1]);
            pa[3] = pkh2(sacc[2 * ks + 1][2], sacc[2 * ks + 1][3]);
#pragma unroll
            for (int nb = 0; nb < 4; nb++) {
                uint32_t bfr[4];
                ldsm4(bfr, vBase + (nb * 16 + bRowL) * 272 + (ks * 16 + bColL) * 2);
                mma16816(oacc[2 * nb],     pa, &bfr[0]);
                mma16816(oacc[2 * nb + 1], pa, &bfr[2]);
            }
        }
        __syncthreads();
    }

    float i0 = 1.0f / l0, i1 = 1.0f / l1;
    int row = q0 + wid * 16 + (lid >> 2);
    __half* d0 = ao + ((size_t)b * SEQ + row) * HID + h * 64;
    __half* d1 = ao + ((size_t)b * SEQ + row + 8) * HID + h * 64;
#pragma unroll
    for (int j = 0; j < 8; j++) {
        int cc = j * 8 + (lid & 3) * 2;
        *(uint32_t*)(d0 + cc) = pkh2(oacc[j][0] * i0, oacc[j][1] * i0);
        *(uint32_t*)(d1 + cc) = pkh2(oacc[j][2] * i1, oacc[j][3] * i1);
    }
}

// ---------------- support kernels ----------------
__global__ void __launch_bounds__(256) f2h_k(const float* __restrict__ in, __half* __restrict__ outp, int n4) {
    int i = blockIdx.x * 256 + threadIdx.x;
    if (i >= n4) return;
    float4 v = ((const float4*)in)[i];
    ((uint2*)outp)[i] = make_uint2(pkh2(v.x, v.y), pkh2(v.z, v.w));
}

__global__ void tconv_k(const float* __restrict__ in, __half* __restrict__ outp, int R, int C) {
    __shared__ float t[32][33];
    in += (size_t)blockIdx.z * R * C;
    outp += (size_t)blockIdx.z * R * C;
    int x = blockIdx.x * 32 + threadIdx.x;
    int y0 = blockIdx.y * 32;
#pragma unroll
    for (int j = 0; j < 32; j += 8)
        t[threadIdx.y + j][threadIdx.x] = in[(size_t)(y0 + threadIdx.y + j) * C + x];
    __syncthreads();
    int ox = y0 + threadIdx.x;
    int oy0 = blockIdx.x * 32;
#pragma unroll
    for (int j = 0; j < 32; j += 8)
        outp[(size_t)(oy0 + threadIdx.y + j) * R + ox] = __float2half_rn(t[threadIdx.x][threadIdx.y + j]);
}

template <bool BOTH>
__global__ void __launch_bounds__(256) ln_k(const float* __restrict__ x, const float* __restrict__ g,
                                            const float* __restrict__ bta,
                                            __half* __restrict__ ob, float* __restrict__ of) {
    __shared__ float red[16], fin[2];
    int tid = threadIdx.x;
    size_t row = blockIdx.x;
    float4 v = ((const float4*)(x + row * HID))[tid];
    float s = v.x + v.y + v.z + v.w;
    float q = v.x * v.x + v.y * v.y + v.z * v.z + v.w * v.w;
#pragma unroll
    for (int o = 16; o; o >>= 1) {
        s += __shfl_xor_sync(0xffffffffu, s, o);
        q += __shfl_xor_sync(0xffffffffu, q, o);
    }
    if ((tid & 31) == 0) { red[tid >> 5] = s; red[8 + (tid >> 5)] = q; }
    __syncthreads();
    if (tid < 8) {
        s = red[tid]; q = red[8 + tid];
#pragma unroll
        for (int o = 4; o; o >>= 1) {
            s += __shfl_xor_sync(0xffu, s, o);
            q += __shfl_xor_sync(0xffu, q, o);
        }
        if (tid == 0) {
            float mu = s * (1.0f / HID);
            fin[0] = mu;
            fin[1] = rsqrtf(q * (1.0f / HID) - mu * mu + 1e-5f);
        }
    }
    __syncthreads();
    float mu = fin[0], rstd = fin[1];
    float4 gv = ((const float4*)g)[tid];
    float4 bv = ((const float4*)bta)[tid];
    float4 o;
    o.x = (v.x - mu) * rstd * gv.x + bv.x;
    o.y = (v.y - mu) * rstd * gv.y + bv.y;
    o.z = (v.z - mu) * rstd * gv.z + bv.z;
    o.w = (v.w - mu) * rstd * gv.w + bv.w;
    ((uint2*)(ob + row * HID))[tid] = make_uint2(pkh2(o.x, o.y), pkh2(o.z, o.w));
    if (BOTH) ((float4*)(of + row * HID))[tid] = o;
}

__global__ void __launch_bounds__(256) gate_k(const float* __restrict__ Wg) {
    int warp = (blockIdx.x * 256 + threadIdx.x) >> 5;
    int lane = threadIdx.x & 31;
    if (warp >= TOK) return;
    const float* xr = g_h2f + (size_t)warp * HID;
    float acc[8] = {0, 0, 0, 0, 0, 0, 0, 0};
    for (int hh = lane; hh < HID; hh += 32) {
        float xv = xr[hh];
        float4 w0 = *(const float4*)(Wg + hh * 8);
        float4 w1 = *(const float4*)(Wg + hh * 8 + 4);
        acc[0] += xv * w0.x; acc[1] += xv * w0.y; acc[2] += xv * w0.z; acc[3] += xv * w0.w;
        acc[4] += xv * w1.x; acc[5] += xv * w1.y; acc[6] += xv * w1.z; acc[7] += xv * w1.w;
    }
#pragma unroll
    for (int o = 16; o; o >>= 1)
#pragma unroll
        for (int e = 0; e < 8; e++) acc[e] += __shfl_xor_sync(0xffffffffu, acc[e], o);
    if (lane == 0) {
        int i0 = 0; float v0 = acc[0];
#pragma unroll
        for (int e = 1; e < 8; e++) if (acc[e] > v0) { v0 = acc[e]; i0 = e; }
        int i1 = -1; float v1 = -3.4e38f;
#pragma unroll
        for (int e = 0; e < 8; e++) if (e != i0 && acc[e] > v1) { v1 = acc[e]; i1 = e; }
        float w0 = 1.0f / (1.0f + __expf(v1 - v0));
        g_topi[2 * warp] = i0; g_topi[2 * warp + 1] = i1;
        g_topw[2 * warp] = w0; g_topw[2 * warp + 1] = 1.0f - w0;
        atomicAdd(&g_cnt[i0], 1);
        atomicAdd(&g_cnt[i1], 1);
    }
}

__global__ void __launch_bounds__(1024) route_k() {
    if (threadIdx.x == 0) {
        g_offs[0] = 0;
        for (int e = 0; e < NEXP; e++) g_offs[e + 1] = g_offs[e] + g_cnt[e];
    }
    __syncthreads();
    for (int idx = threadIdx.x; idx < TOK * 2; idx += 1024) {
        int e = g_topi[idx];
        int pos = atomicAdd(&g_cur[e], 1);
        int slot = g_offs[e] + pos;
        g_slottok[slot] = idx >> 1;
        g_slotof[idx] = slot;
    }
}

__global__ void __launch_bounds__(256) combine_k(float* __restrict__ outp) {
    int t = blockIdx.x;
    int j = threadIdx.x;
    float w0 = g_topw[2 * t], w1 = g_topw[2 * t + 1];
    size_t s0 = g_slotof[2 * t], s1 = g_slotof[2 * t + 1];
    float4 r  = ((const float4*)(g_xattn + (size_t)t * HID))[j];
    float4 y0 = ((const float4*)(g_Y2 + s0 * HID))[j];
    float4 y1 = ((const float4*)(g_Y2 + s1 * HID))[j];
    r.x += w0 * y0.x + w1 * y1.x;
    r.y += w0 * y0.y + w1 * y1.y;
    r.z += w0 * y0.z + w1 * y1.z;
    r.w += w0 * y0.w + w1 * y1.w;
    ((float4*)(outp + (size_t)t * HID))[j] = r;
}

#define SYM(p, s) void* p; cudaGetSymbolAddress(&p, s)

extern "C" void kernel_launch(void* const* d_in, const int* in_sizes, int n_in,
                              void* d_out, int out_size) {
    const float* x     = (const float*)d_in[0];
    const float* ln1_g = (const float*)d_in[1];
    const float* ln1_b = (const float*)d_in[2];
    const float* qkv_w = (const float*)d_in[3];
    const float* qkv_b = (const float*)d_in[4];
    const float* out_w = (const float*)d_in[5];
    const float* out_b = (const float*)d_in[6];
    const float* ln2_g = (const float*)d_in[7];
    const float* ln2_b = (const float*)d_in[8];
    const float* Wg    = (const float*)d_in[9];
    const float* W1    = (const float*)d_in[10];
    const float* b1    = (const float*)d_in[11];
    const float* W2    = (const float*)d_in[12];
    const float* b2    = (const float*)d_in[13];
    float* outp = (float*)d_out;

    SYM(p_hln, gb_hln);   SYM(p_qkvw, gb_qkvw); SYM(p_outw, gb_outw);
    SYM(p_w1t, gb_w1t);   SYM(p_w2t, gb_w2t);   SYM(p_qkv, gb_qkv);
    SYM(p_vT, gb_vT);     SYM(p_ao, gb_ao);     SYM(p_h2b, gb_h2);
    SYM(p_H1, gb_H1);     SYM(p_xattn, g_xattn); SYM(p_h2f, g_h2f);
    SYM(p_Y2, g_Y2);      SYM(p_cnt, g_cnt);    SYM(p_cur, g_cur);
    SYM(p_slottok, g_slottok); SYM(p_offs, g_offs);

    constexpr int GEMM_SMEM = STAGES3 * (128 + 128) * 144;  // 110592
    cudaFuncSetAttribute(hgemm<0, 128>, cudaFuncAttributeMaxDynamicSharedMemorySize, GEMM_SMEM);
    cudaFuncSetAttribute(hgemm<1, 128>, cudaFuncAttributeMaxDynamicSharedMemorySize, GEMM_SMEM);
    cudaFuncSetAttribute(hgemm<4, 128>, cudaFuncAttributeMaxDynamicSharedMemorySize, GEMM_SMEM);
    cudaFuncSetAttribute(hgemm<5, 128>, cudaFuncAttributeMaxDynamicSharedMemorySize, GEMM_SMEM);
    constexpr int FLASH_SMEM = (128 * 72 * 2) * 3 + (64 * 136 * 2) * 2;  // 90112
    cudaFuncSetAttribute(flash_k, cudaFuncAttributeMaxDynamicSharedMemorySize, FLASH_SMEM);

    cudaStream_t s2;
    cudaStreamCreateWithFlags(&s2, cudaStreamNonBlocking);
    cudaEvent_t evFork, evQkvw, evJoin;
    cudaEventCreateWithFlags(&evFork, cudaEventDisableTiming);
    cudaEventCreateWithFlags(&evQkvw, cudaEventDisableTiming);
    cudaEventCreateWithFlags(&evJoin, cudaEventDisableTiming);

    cudaEventRecord(evFork, 0);
    cudaStreamWaitEvent(s2, evFork, 0);

    dim3 tb(32, 8);
    // side stream: qkv_w convert first (joined early), then the rest
    f2h_k<<<(3 * HID * HID / 4 + 255) / 256, 256, 0, s2>>>(qkv_w, (__half*)p_qkvw, 3 * HID * HID / 4);
    cudaEventRecord(evQkvw, s2);
    tconv_k<<<dim3(FDIM / 32, HID / 32, NEXP), tb, 0, s2>>>(W1, (__half*)p_w1t, HID, FDIM);
    tconv_k<<<dim3(HID / 32, FDIM / 32, NEXP), tb, 0, s2>>>(W2, (__half*)p_w2t, FDIM, HID);
    f2h_k<<<(HID * HID / 4 + 255) / 256, 256, 0, s2>>>(out_w, (__half*)p_outw, HID * HID / 4);
    cudaMemsetAsync(p_cnt, 0, NEXP * sizeof(int), s2);
    cudaMemsetAsync(p_cur, 0, NEXP * sizeof(int), s2);
    cudaEventRecord(evJoin, s2);

    // main stream: LN1 overlaps the qkv_w conversion
    ln_k<false><<<TOK, 256>>>(x, ln1_g, ln1_b, (__half*)p_hln, nullptr);
    cudaStreamWaitEvent(0, evQkvw, 0);

    hgemm<0, 128><<<dim3(3 * HID / 128, TOK / 128, 1), 256, GEMM_SMEM>>>(
        (const __half*)p_hln, (const __half*)p_qkvw, p_qkv,
        TOK, 3 * HID, HID, HID, HID, 3 * HID, qkv_b, nullptr, nullptr, nullptr);

    flash_k<<<dim3(SEQ / 128, 2 * NHEAD), 256, FLASH_SMEM>>>(
        (const __half*)p_qkv, (const __half*)p_vT, (__half*)p_ao);

    cudaStreamWaitEvent(0, evJoin, 0);

    hgemm<1, 128><<<dim3(HID / 128, TOK / 128, 1), 256, GEMM_SMEM>>>(
        (const __half*)p_ao, (const __half*)p_outw, p_xattn,
        TOK, HID, HID, HID, HID, HID, out_b, x, nullptr, nullptr);

    ln_k<true><<<TOK, 256>>>((const float*)p_xattn, ln2_g, ln2_b,
                             (__half*)p_h2b, (float*)p_h2f);

    gate_k<<<TOK / 8, 256>>>(Wg);
    route_k<<<1, 1024>>>();

    // per-expert slot count is bounded by TOK (each token contributes an
    // expert at most once) => y = TOK/128 = 32 covers every possible routing.
    hgemm<4, 128><<<dim3(FDIM / 128, TOK / 128, NEXP), 256, GEMM_SMEM>>>(
        (const __half*)p_h2b, (const __half*)p_w1t, p_H1,
        0, FDIM, HID, HID, HID, FDIM, b1, nullptr, (const int*)p_slottok, (const int*)p_offs);

    hgemm<5, 128><<<dim3(HID / 128, TOK / 128, NEXP), 256, GEMM_SMEM>>>(
        (const __half*)p_H1, (const __half*)p_w2t, p_Y2,
        0, HID, FDIM, FDIM, FDIM, HID, b2, nullptr, nullptr, (const int*)p_offs);

    combine_k<<<TOK, 256>>>(outp);

    cudaStreamDestroy(s2);
    cudaEventDestroy(evFork);
    cudaEventDestroy(evQkvw);
    cudaEventDestroy(evJoin);
}